// round 13
// baseline (speedup 1.0000x reference)
#include <cuda_runtime.h>
#include <cuda_fp16.h>
#include <math.h>
#include <cstdint>

#define BB 8
#define LL 1024
#define DD 1024
#define HH 16
#define DK 64
#define ROWS_TOT (BB*LL)          // 8192

// Scratch (device globals)
__device__ __half g_qh [(size_t)ROWS_TOT * DD];   // fp16 q heads (scaled 1/8)
__device__ __half g_kh [(size_t)ROWS_TOT * DD];   // fp16 k heads
__device__ __half g_vhT[(size_t)ROWS_TOT * DD];   // [b][h][d][token] fp16
__device__ __half g_ctx[(size_t)ROWS_TOT * DD];   // fp16
__device__ float  g_proj[(size_t)ROWS_TOT * DD];
__device__ __half g_as [(size_t)ROWS_TOT * DD];
__device__ __half g_ws [(size_t)DD * DD];

// ---------------------------------------------------------------------------
// helpers
// ---------------------------------------------------------------------------
__device__ __forceinline__ uint32_t smem_u32(const void* p) {
    uint32_t a;
    asm("{ .reg .u64 t; cvta.to.shared.u64 t, %1; cvt.u32.u64 %0, t; }" : "=r"(a) : "l"(p));
    return a;
}
__device__ __forceinline__ void cp16(uint32_t dst, const void* src) {
    asm volatile("cp.async.cg.shared.global [%0], [%1], 16;" :: "r"(dst), "l"(src));
}
#define CP_COMMIT asm volatile("cp.async.commit_group;" ::: "memory")
#define CP_WAIT2  asm volatile("cp.async.wait_group 2;" ::: "memory")
#define CP_WAIT1  asm volatile("cp.async.wait_group 1;" ::: "memory")
#define CP_WAIT0  asm volatile("cp.async.wait_group 0;" ::: "memory")

__device__ __forceinline__ void mma_f16(float* c, const uint32_t* a, const uint32_t* b) {
    asm volatile(
        "mma.sync.aligned.m16n8k16.row.col.f32.f16.f16.f32 "
        "{%0,%1,%2,%3},{%4,%5,%6,%7},{%8,%9},{%0,%1,%2,%3};"
        : "+f"(c[0]), "+f"(c[1]), "+f"(c[2]), "+f"(c[3])
        : "r"(a[0]), "r"(a[1]), "r"(a[2]), "r"(a[3]), "r"(b[0]), "r"(b[1]));
}
__device__ __forceinline__ void ldsm4(uint32_t& r0, uint32_t& r1, uint32_t& r2,
                                      uint32_t& r3, uint32_t addr) {
    asm volatile("ldmatrix.sync.aligned.m8n8.x4.shared.b16 {%0,%1,%2,%3}, [%4];"
                 : "=r"(r0), "=r"(r1), "=r"(r2), "=r"(r3) : "r"(addr));
}
__device__ __forceinline__ void ldsm2(uint32_t& r0, uint32_t& r1, uint32_t addr) {
    asm volatile("ldmatrix.sync.aligned.m8n8.x2.shared.b16 {%0,%1}, [%2];"
                 : "=r"(r0), "=r"(r1) : "r"(addr));
}

// f32 -> fp16 convert
__global__ __launch_bounds__(256) void conv_f16(
    const float* __restrict__ x, __half* __restrict__ hi, int n4)
{
    int i = blockIdx.x * blockDim.x + threadIdx.x;
    if (i >= n4) return;
    float4 v = ((const float4*)x)[i];
    ((__half2*)hi)[i * 2]     = __floats2half2_rn(v.x, v.y);
    ((__half2*)hi)[i * 2 + 1] = __floats2half2_rn(v.z, v.w);
}

// ===========================================================================
// single-term fp16 GEMM, 128x256 tile, BK=32, 512 threads (16 warps: 2m x 8n,
// warp tile 64x32). Output modes: outT transposed fp16 | outH fp16 | outF fp32
// smem: A 128x40h (10240B) + B 256x40h (20480B) per buf, double buffered;
// transpose epilogue stages 256x136h = 69632B -> GEMM1_SMEM 71680
// ===========================================================================
#define APL_B 10240
#define BUFB  30720
#define GEMM1_SMEM 71680

__global__ __launch_bounds__(512) void gemm_f16_1t(
    const __half* __restrict__ A, const __half* __restrict__ B,
    const float* __restrict__ bias, const float* __restrict__ npm, float scale,
    float* __restrict__ outF, __half* __restrict__ outH, __half* __restrict__ outT)
{
    extern __shared__ char sm[];
    const uint32_t smb = smem_u32(sm);
    const int tid = threadIdx.x, wid = tid >> 5, lane = tid & 31;
    const int g = lane >> 2, tg = lane & 3;
    const int bm = blockIdx.y * 128, bn = blockIdx.x * 256;
    const int wm = (wid & 1) * 64, wn = (wid >> 1) * 32;
    const int lrow = lane & 15, lkh = (lane >> 4) * 16;

    const __half* Ap = A + (size_t)bm * DD;
    const __half* Bp = B + (size_t)bn * DD;
    const int arow = tid >> 2, ac = tid & 3;

    float acc[4][4][4];
#pragma unroll
    for (int mi = 0; mi < 4; mi++)
#pragma unroll
        for (int ni = 0; ni < 4; ni++)
#pragma unroll
            for (int r = 0; r < 4; r++) acc[mi][ni][r] = 0.f;

    // prefill kt=0
    cp16(smb + arow * 80 + ac * 16, Ap + (size_t)arow * DD + ac * 8);
#pragma unroll
    for (int j = 0; j < 2; j++) {
        int idx = tid + 512 * j;
        int brow = idx >> 2, bc = idx & 3;
        cp16(smb + APL_B + brow * 80 + bc * 16, Bp + (size_t)brow * DD + bc * 8);
    }
    CP_COMMIT;

    for (int kt = 0; kt < 32; kt++) {
        if (kt < 31) {
            uint32_t nb = smb + ((kt + 1) & 1) * BUFB;
            cp16(nb + arow * 80 + ac * 16,
                 Ap + (size_t)arow * DD + (kt + 1) * 32 + ac * 8);
#pragma unroll
            for (int j = 0; j < 2; j++) {
                int idx = tid + 512 * j;
                int brow = idx >> 2, bc = idx & 3;
                cp16(nb + APL_B + brow * 80 + bc * 16,
                     Bp + (size_t)brow * DD + (kt + 1) * 32 + bc * 8);
            }
            CP_COMMIT;
            CP_WAIT1;
        } else {
            CP_WAIT0;
        }
        __syncthreads();

        const uint32_t bufb = smb + (kt & 1) * BUFB;
#pragma unroll
        for (int ks = 0; ks < 2; ks++) {
            uint32_t a_h[4][4], b4a[4], b4b[4], b_h[4][2];
#pragma unroll
            for (int mi = 0; mi < 4; mi++)
                ldsm4(a_h[mi][0], a_h[mi][1], a_h[mi][2], a_h[mi][3],
                      bufb + (wm + mi * 16 + lrow) * 80 + ks * 32 + lkh);
            ldsm4(b4a[0], b4a[1], b4a[2], b4a[3],
                  bufb + APL_B + (wn + lrow) * 80 + ks * 32 + lkh);
            ldsm4(b4b[0], b4b[1], b4b[2], b4b[3],
                  bufb + APL_B + (wn + 16 + lrow) * 80 + ks * 32 + lkh);
            b_h[0][0] = b4a[0]; b_h[0][1] = b4a[2];
            b_h[1][0] = b4a[1]; b_h[1][1] = b4a[3];
            b_h[2][0] = b4b[0]; b_h[2][1] = b4b[2];
            b_h[3][0] = b4b[1]; b_h[3][1] = b4b[3];
#pragma unroll
            for (int mi = 0; mi < 4; mi++)
#pragma unroll
                for (int ni = 0; ni < 4; ni++)
                    mma_f16(acc[mi][ni], a_h[mi], b_h[ni]);
        }
        __syncthreads();
    }

    if (outT) {
        __half* smT = (__half*)sm;
#pragma unroll
        for (int mi = 0; mi < 4; mi++) {
            int r = wm + mi * 16 + g;
            float nv0 = npm[bm + r] * scale, nv1 = npm[bm + r + 8] * scale;
#pragma unroll
            for (int ni = 0; ni < 4; ni++) {
                int c = wn + ni * 8 + 2 * tg;
                float b0 = bias[bn + c], b1 = bias[bn + c + 1];
                smT[c * 136 + r]           = __float2half((acc[mi][ni][0] + b0) * nv0);
                smT[(c + 1) * 136 + r]     = __float2half((acc[mi][ni][1] + b1) * nv0);
                smT[c * 136 + r + 8]       = __float2half((acc[mi][ni][2] + b0) * nv1);
                smT[(c + 1) * 136 + r + 8] = __float2half((acc[mi][ni][3] + b1) * nv1);
            }
        }
        __syncthreads();
        const int b = bm >> 10, token0 = bm & 1023;
#pragma unroll
        for (int p = 0; p < 8; p++) {
            int cr = (tid >> 4) + p * 32;      // 0..255
            int unit = tid & 15;
            int C = bn + cr;
            int h = C >> 6, d = C & 63;
            size_t dst = ((size_t)(b * 16 + h) * 64 + d) * 1024 + token0 + unit * 8;
            *(uint4*)&outT[dst] = *(const uint4*)&smT[cr * 136 + unit * 8];
        }
    } else if (outH) {
#pragma unroll
        for (int mi = 0; mi < 4; mi++) {
            int r0 = bm + wm + mi * 16 + g, r1 = r0 + 8;
            float nv0 = npm[r0] * scale, nv1 = npm[r1] * scale;
#pragma unroll
            for (int ni = 0; ni < 4; ni++) {
                int c0 = bn + wn + ni * 8 + 2 * tg;
                float b0 = bias[c0], b1 = bias[c0 + 1];
                *(__half2*)&outH[(size_t)r0 * DD + c0] =
                    __floats2half2_rn((acc[mi][ni][0] + b0) * nv0, (acc[mi][ni][1] + b1) * nv0);
                *(__half2*)&outH[(size_t)r1 * DD + c0] =
                    __floats2half2_rn((acc[mi][ni][2] + b0) * nv1, (acc[mi][ni][3] + b1) * nv1);
            }
        }
    } else {
#pragma unroll
        for (int mi = 0; mi < 4; mi++) {
            int r0 = bm + wm + mi * 16 + g, r1 = r0 + 8;
            float nv0 = npm[r0] * scale, nv1 = npm[r1] * scale;
#pragma unroll
            for (int ni = 0; ni < 4; ni++) {
                int c0 = bn + wn + ni * 8 + 2 * tg;
                float b0 = bias[c0], b1 = bias[c0 + 1];
                *(float2*)&outF[(size_t)r0 * DD + c0] =
                    make_float2((acc[mi][ni][0] + b0) * nv0, (acc[mi][ni][1] + b1) * nv0);
                *(float2*)&outF[(size_t)r1 * DD + c0] =
                    make_float2((acc[mi][ni][2] + b0) * nv1, (acc[mi][ni][3] + b1) * nv1);
            }
        }
    }
}

// ===========================================================================
// Fused attention (R11 structure): block = (b,h) x 32 q-rows, 512 threads
// S = QK^T fp16 (K quad-buffered, ldmatrix) -> 2-pass no-max softmax
// (mask folded into exp pass; P fp16 smem) -> PV fp16 mma (V^T quad-buffered)
// smem map: S f32 [0,131584) | Q @131584 (4608) | K 4x18432 @136192 = 209920
// overlays:  VT 4x17408 @0 (PV) | P 32x2096 @131584 (after S-phase)
// ===========================================================================
#define SSTR 1028
#define QOFF 131584
#define KOFF 136192
#define KBUF 18432
#define ATT_SMEM 209920
#define POFF QOFF
#define PSTRB 2096
#define VTSTRB 272
#define VTBUF 17408

__global__ __launch_bounds__(512) void attn_kernel(
    const __half* __restrict__ qh, const __half* __restrict__ kh,
    const __half* __restrict__ vhT, const int* __restrict__ mask,
    float* __restrict__ attn, __half* __restrict__ ctx)
{
    extern __shared__ char sm[];
    const uint32_t smb = smem_u32(sm);
    float* S = (float*)sm;

    const int tid = threadIdx.x, wid = tid >> 5, lane = tid & 31;
    const int g = lane >> 2, tg = lane & 3;
    const int lrow = lane & 15, lkh = (lane >> 4) * 16;
    const int bh = blockIdx.x;
    const int b = bh >> 4, h = bh & 15;
    const int q0 = blockIdx.y * 32;
    const int wq = wid & 1;
    const int wk = wid >> 1;

    const __half* qp_g = qh + ((size_t)b * LL + q0) * DD + h * DK;
    const __half* kp_g = kh + (size_t)b * LL * DD + h * DK;
    const __half* vTp = vhT + (size_t)bh * DK * LL;
    float* attnBase = attn + ((size_t)bh * LL + q0) * LL;

    // Q load + K0 (group 1), K1 (group 2)
    if (tid < 256) {
        int row = tid >> 3, c8 = tid & 7;
        cp16(smb + QOFF + row * 144 + c8 * 16, qp_g + (size_t)row * DD + c8 * 8);
    }
#pragma unroll
    for (int j = 0; j < 2; j++) {
        int idx = tid + 512 * j;
        int row = idx >> 3, c8 = idx & 7;
        cp16(smb + KOFF + row * 144 + c8 * 16, kp_g + (size_t)row * DD + c8 * 8);
    }
    CP_COMMIT;
#pragma unroll
    for (int j = 0; j < 2; j++) {
        int idx = tid + 512 * j;
        int row = idx >> 3, c8 = idx & 7;
        cp16(smb + KOFF + KBUF + row * 144 + c8 * 16,
             kp_g + (size_t)(128 + row) * DD + c8 * 8);
    }
    CP_COMMIT;

    // ---- S = Q K^T over 8 chunks, quad-buffered K ----
    for (int kc = 0; kc < 8; kc++) {
        if (kc < 6) {
#pragma unroll
            for (int j = 0; j < 2; j++) {
                int idx = tid + 512 * j;
                int row = idx >> 3, c8 = idx & 7;
                cp16(smb + KOFF + ((kc + 2) & 3) * KBUF + row * 144 + c8 * 16,
                     kp_g + (size_t)((kc + 2) * 128 + row) * DD + c8 * 8);
            }
            CP_COMMIT;
            CP_WAIT2;
        } else if (kc == 6) {
            CP_WAIT1;
        } else {
            CP_WAIT0;
        }
        __syncthreads();

        const uint32_t kb = smb + KOFF + (kc & 3) * KBUF;
        float sacc[2][4];
#pragma unroll
        for (int ni = 0; ni < 2; ni++)
#pragma unroll
            for (int r = 0; r < 4; r++) sacc[ni][r] = 0.f;

#pragma unroll
        for (int ks = 0; ks < 4; ks++) {
            uint32_t a_h[4], b4[4], b_h[2][2];
            ldsm4(a_h[0], a_h[1], a_h[2], a_h[3],
                  smb + QOFF + (wq * 16 + lrow) * 144 + ks * 32 + lkh);
            ldsm4(b4[0], b4[1], b4[2], b4[3],
                  kb + (wk * 16 + lrow) * 144 + ks * 32 + lkh);
            b_h[0][0] = b4[0]; b_h[0][1] = b4[2];
            b_h[1][0] = b4[1]; b_h[1][1] = b4[3];
            mma_f16(sacc[0], a_h, b_h[0]);
            mma_f16(sacc[1], a_h, b_h[1]);
        }
#pragma unroll
        for (int ni = 0; ni < 2; ni++) {
            int c = kc * 128 + wk * 16 + ni * 8 + 2 * tg;
            *(float2*)&S[(wq * 16 + g) * SSTR + c]     = make_float2(sacc[ni][0], sacc[ni][1]);
            *(float2*)&S[(wq * 16 + g + 8) * SSTR + c] = make_float2(sacc[ni][2], sacc[ni][3]);
        }
    }
    __syncthreads();

    // ---- 2-pass no-max softmax; mask folded into exp pass ----
#pragma unroll
    for (int rr = 0; rr < 2; rr++) {
        int r = wid * 2 + rr;
        float* Sr = S + r * SSTR;
        const int* mr = mask + ((size_t)b * LL + q0 + r) * LL;
        float sum = 0.f;
        for (int c = lane; c < 1024; c += 32) {
            float e = mr[c] ? 0.f : __expf(Sr[c]);
            Sr[c] = e;
            sum += e;
        }
#pragma unroll
        for (int o = 16; o; o >>= 1) sum += __shfl_xor_sync(0xffffffffu, sum, o);
        float inv = 1.f / sum;
        float* dst = attnBase + (size_t)r * LL;
        __half* Pr = (__half*)(sm + POFF + r * PSTRB);
        for (int c = lane; c < 1024; c += 32) {
            float p = Sr[c] * inv;
            dst[c] = p;
            Pr[c] = __float2half(p);
        }
    }
    __syncthreads();   // P complete; S region dead -> VT buffers

    // prefetch V^T chunks 0,1 (groups 1,2)
#pragma unroll
    for (int j = 0; j < 2; j++) {
        int idx = tid + 512 * j;
        int d = idx >> 4, tk = idx & 15;
        cp16(smb + d * VTSTRB + tk * 16, vTp + (size_t)d * LL + tk * 8);
    }
    CP_COMMIT;
#pragma unroll
    for (int j = 0; j < 2; j++) {
        int idx = tid + 512 * j;
        int d = idx >> 4, tk = idx & 15;
        cp16(smb + VTBUF + d * VTSTRB + tk * 16, vTp + (size_t)d * LL + 128 + tk * 8);
    }
    CP_COMMIT;

    // ---- PV: fp16 mma, warp tile 16q x 8d, quad-buffered V^T ----
    float pacc[4] = {0.f, 0.f, 0.f, 0.f};
    for (int vc = 0; vc < 8; vc++) {
        if (vc < 6) {
#pragma unroll
            for (int j = 0; j < 2; j++) {
                int idx = tid + 512 * j;
                int d = idx >> 4, tk = idx & 15;
                cp16(smb + ((vc + 2) & 3) * VTBUF + d * VTSTRB + tk * 16,
                     vTp + (size_t)d * LL + (vc + 2) * 128 + tk * 8);
            }
            CP_COMMIT;
            CP_WAIT2;
        } else if (vc == 6) {
            CP_WAIT1;
        } else {
            CP_WAIT0;
        }
        __syncthreads();

        const uint32_t vtb = smb + (vc & 3) * VTBUF;
        const uint32_t pb = smb + POFF + (wq * 16) * PSTRB + vc * 256;
#pragma unroll
        for (int kk = 0; kk < 8; kk++) {
            uint32_t a[4], bfr[2];
            ldsm4(a[0], a[1], a[2], a[3], pb + lrow * PSTRB + kk * 32 + lkh);
            ldsm2(bfr[0], bfr[1],
                  vtb + (wk * 8 + (lane & 7)) * VTSTRB + kk * 32 + ((lane >> 3) & 1) * 16);
            mma_f16(pacc, a, bfr);
        }
    }

    {
        int c = h * DK + wk * 8 + 2 * tg;
        size_t r0 = (size_t)b * LL + q0 + wq * 16 + g;
        *(__half2*)&ctx[r0 * DD + c]       = __floats2half2_rn(pacc[0], pacc[1]);
        *(__half2*)&ctx[(r0 + 8) * DD + c] = __floats2half2_rn(pacc[2], pacc[3]);
    }
}

// ---------------------------------------------------------------------------
// LayerNorm(proj + residual) * g + b
// ---------------------------------------------------------------------------
__global__ __launch_bounds__(256) void ln_kernel(
    const float* __restrict__ proj, const float* __restrict__ resid,
    const float* __restrict__ gam, const float* __restrict__ bet,
    float* __restrict__ out)
{
    __shared__ float red[8];
    const int row = blockIdx.x;
    const int tid = threadIdx.x;
    const int c0 = tid * 4;
    const int lane = tid & 31, wid = tid >> 5;

    float4 pv = *(const float4*)(proj + (size_t)row * DD + c0);
    float4 rv = *(const float4*)(resid + (size_t)row * DD + c0);
    float x0 = pv.x + rv.x, x1 = pv.y + rv.y, x2 = pv.z + rv.z, x3 = pv.w + rv.w;

    float s = x0 + x1 + x2 + x3;
#pragma unroll
    for (int o = 16; o; o >>= 1) s += __shfl_xor_sync(0xffffffffu, s, o);
    if (lane == 0) red[wid] = s;
    __syncthreads();
    float tot = (lane < 8) ? red[lane] : 0.f;
#pragma unroll
    for (int o = 4; o; o >>= 1) tot += __shfl_xor_sync(0xffffffffu, tot, o);
    tot = __shfl_sync(0xffffffffu, tot, 0);
    float mean = tot * (1.f / 1024.f);

    float d0 = x0 - mean, d1 = x1 - mean, d2 = x2 - mean, d3 = x3 - mean;
    float sq = d0 * d0 + d1 * d1 + d2 * d2 + d3 * d3;
#pragma unroll
    for (int o = 16; o; o >>= 1) sq += __shfl_xor_sync(0xffffffffu, sq, o);
    __syncthreads();
    if (lane == 0) red[wid] = sq;
    __syncthreads();
    float tot2 = (lane < 8) ? red[lane] : 0.f;
#pragma unroll
    for (int o = 4; o; o >>= 1) tot2 += __shfl_xor_sync(0xffffffffu, tot2, o);
    tot2 = __shfl_sync(0xffffffffu, tot2, 0);
    float k = rsqrtf(tot2 * (1.f / 1024.f) + 1e-5f);

    float4 gv = *(const float4*)(gam + c0);
    float4 bv = *(const float4*)(bet + c0);
    float4 ov;
    ov.x = d0 * k * gv.x + bv.x;
    ov.y = d1 * k * gv.y + bv.y;
    ov.z = d2 * k * gv.z + bv.z;
    ov.w = d3 * k * gv.w + bv.w;
    *(float4*)&out[(size_t)row * DD + c0] = ov;
}

// ---------------------------------------------------------------------------
extern "C" void kernel_launch(void* const* d_in, const int* in_sizes, int n_in,
                              void* d_out, int out_size)
{
    const float* q    = (const float*)d_in[0];
    const float* k    = (const float*)d_in[1];
    const float* v    = (const float*)d_in[2];
    const int*   mask = (const int*)  d_in[3];
    const float* npm  = (const float*)d_in[4];
    const float* Wq   = (const float*)d_in[5];
    const float* bq   = (const float*)d_in[6];
    const float* Wk   = (const float*)d_in[7];
    const float* bk   = (const float*)d_in[8];
    const float* Wv   = (const float*)d_in[9];
    const float* bv   = (const float*)d_in[10];
    const float* Wf   = (const float*)d_in[11];
    const float* bf   = (const float*)d_in[12];
    const float* ln_g = (const float*)d_in[13];
    const float* ln_b = (const float*)d_in[14];

    float* out  = (float*)d_out;
    float* attn = out + (size_t)BB * LL * DD;

    __half *qh, *kh, *vhT, *ctx, *as, *ws;
    float *proj;
    cudaGetSymbolAddress((void**)&qh,  g_qh);
    cudaGetSymbolAddress((void**)&kh,  g_kh);
    cudaGetSymbolAddress((void**)&vhT, g_vhT);
    cudaGetSymbolAddress((void**)&ctx, g_ctx);
    cudaGetSymbolAddress((void**)&proj, g_proj);
    cudaGetSymbolAddress((void**)&as,  g_as);
    cudaGetSymbolAddress((void**)&ws,  g_ws);

    cudaFuncSetAttribute(gemm_f16_1t, cudaFuncAttributeMaxDynamicSharedMemorySize, GEMM1_SMEM);
    cudaFuncSetAttribute(attn_kernel, cudaFuncAttributeMaxDynamicSharedMemorySize, ATT_SMEM);

    const int nA4 = ROWS_TOT * DD / 4;
    const int nW4 = DD * DD / 4;
    dim3 gG(DD / 256, ROWS_TOT / 128);   // (4, 64)

    // Q projection (scale 1/8 folded) -> fp16
    conv_f16<<<(nA4 + 255) / 256, 256>>>(q, as, nA4);
    conv_f16<<<(nW4 + 255) / 256, 256>>>(Wq, ws, nW4);
    gemm_f16_1t<<<gG, 512, GEMM1_SMEM>>>(as, ws, bq, npm, 0.125f, nullptr, qh, nullptr);
    // K projection -> fp16
    conv_f16<<<(nA4 + 255) / 256, 256>>>(k, as, nA4);
    conv_f16<<<(nW4 + 255) / 256, 256>>>(Wk, ws, nW4);
    gemm_f16_1t<<<gG, 512, GEMM1_SMEM>>>(as, ws, bk, npm, 1.0f, nullptr, kh, nullptr);
    // V projection -> transposed fp16 vhT
    conv_f16<<<(nA4 + 255) / 256, 256>>>(v, as, nA4);
    conv_f16<<<(nW4 + 255) / 256, 256>>>(Wv, ws, nW4);
    gemm_f16_1t<<<gG, 512, GEMM1_SMEM>>>(as, ws, bv, npm, 1.0f, nullptr, nullptr, vhT);

    // Fused attention (ctx out as fp16)
    attn_kernel<<<dim3(BB * HH, LL / 32), 512, ATT_SMEM>>>(
        qh, kh, vhT, mask, attn, ctx);

    // Output projection (ctx fp16 direct) -> fp32, then LN
    conv_f16<<<(nW4 + 255) / 256, 256>>>(Wf, ws, nW4);
    gemm_f16_1t<<<gG, 512, GEMM1_SMEM>>>(ctx, ws, bf, npm, 1.0f, proj, nullptr, nullptr);

    ln_kernel<<<ROWS_TOT, 256>>>(proj, q, ln_g, ln_b, out);
}

// round 14
// speedup vs baseline: 1.4350x; 1.4350x over previous
#include <cuda_runtime.h>
#include <cuda_fp16.h>
#include <math.h>
#include <cstdint>

#define BB 8
#define LL 1024
#define DD 1024
#define HH 16
#define DK 64
#define ROWS_TOT (BB*LL)          // 8192

// Scratch (device globals)
__device__ __half g_qh [(size_t)ROWS_TOT * DD];   // fp16 q heads (scaled 1/8)
__device__ __half g_kh [(size_t)ROWS_TOT * DD];   // fp16 k heads
__device__ __half g_vhT[(size_t)ROWS_TOT * DD];   // [b][h][d][token] fp16
__device__ __half g_ctx[(size_t)ROWS_TOT * DD];   // fp16
__device__ float  g_proj[(size_t)ROWS_TOT * DD];
__device__ __half g_as [(size_t)ROWS_TOT * DD];
__device__ __half g_ws [(size_t)DD * DD];

// ---------------------------------------------------------------------------
// helpers
// ---------------------------------------------------------------------------
__device__ __forceinline__ uint32_t smem_u32(const void* p) {
    uint32_t a;
    asm("{ .reg .u64 t; cvta.to.shared.u64 t, %1; cvt.u32.u64 %0, t; }" : "=r"(a) : "l"(p));
    return a;
}
__device__ __forceinline__ void cp16(uint32_t dst, const void* src) {
    asm volatile("cp.async.cg.shared.global [%0], [%1], 16;" :: "r"(dst), "l"(src));
}
#define CP_COMMIT asm volatile("cp.async.commit_group;" ::: "memory")
#define CP_WAIT2  asm volatile("cp.async.wait_group 2;" ::: "memory")
#define CP_WAIT1  asm volatile("cp.async.wait_group 1;" ::: "memory")
#define CP_WAIT0  asm volatile("cp.async.wait_group 0;" ::: "memory")

__device__ __forceinline__ void mma_f16(float* c, const uint32_t* a, const uint32_t* b) {
    asm volatile(
        "mma.sync.aligned.m16n8k16.row.col.f32.f16.f16.f32 "
        "{%0,%1,%2,%3},{%4,%5,%6,%7},{%8,%9},{%0,%1,%2,%3};"
        : "+f"(c[0]), "+f"(c[1]), "+f"(c[2]), "+f"(c[3])
        : "r"(a[0]), "r"(a[1]), "r"(a[2]), "r"(a[3]), "r"(b[0]), "r"(b[1]));
}
__device__ __forceinline__ void ldsm4(uint32_t& r0, uint32_t& r1, uint32_t& r2,
                                      uint32_t& r3, uint32_t addr) {
    asm volatile("ldmatrix.sync.aligned.m8n8.x4.shared.b16 {%0,%1,%2,%3}, [%4];"
                 : "=r"(r0), "=r"(r1), "=r"(r2), "=r"(r3) : "r"(addr));
}
__device__ __forceinline__ void ldsm2(uint32_t& r0, uint32_t& r1, uint32_t addr) {
    asm volatile("ldmatrix.sync.aligned.m8n8.x2.shared.b16 {%0,%1}, [%2];"
                 : "=r"(r0), "=r"(r1) : "r"(addr));
}

// f32 -> fp16 convert
__global__ __launch_bounds__(256) void conv_f16(
    const float* __restrict__ x, __half* __restrict__ hi, int n4)
{
    int i = blockIdx.x * blockDim.x + threadIdx.x;
    if (i >= n4) return;
    float4 v = ((const float4*)x)[i];
    ((__half2*)hi)[i * 2]     = __floats2half2_rn(v.x, v.y);
    ((__half2*)hi)[i * 2 + 1] = __floats2half2_rn(v.z, v.w);
}

// ===========================================================================
// single-term fp16 GEMM (ldmatrix fragments). Output modes:
//   outT: transposed fp16 (V proj -> vhT) | outH: planar fp16 (Q/K) | outF: fp32
// 128x128 tile, BK=32, 512 threads
// ===========================================================================
#define PL_E 5120
#define PL_B (PL_E*2)
#define BUF1_B (2*PL_B)
#define GEMM1_SMEM (2*BUF1_B)

__global__ __launch_bounds__(512) void gemm_f16_1t(
    const __half* __restrict__ A, const __half* __restrict__ B,
    const float* __restrict__ bias, const float* __restrict__ npm, float scale,
    float* __restrict__ outF, __half* __restrict__ outH, __half* __restrict__ outT)
{
    extern __shared__ char sm[];
    const uint32_t smb = smem_u32(sm);
    const int tid = threadIdx.x, wid = tid >> 5, lane = tid & 31;
    const int g = lane >> 2, tg = lane & 3;
    const int bm = blockIdx.y * 128, bn = blockIdx.x * 128;
    const int wm = (wid & 1) * 64, wn = (wid >> 1) * 16;
    const int lrow = lane & 15, lkh = (lane >> 4) * 16;

    const __half* srcs[2] = { A + (size_t)bm * DD, B + (size_t)bn * DD };
    const int frow = tid >> 2, fc = tid & 3;

    float acc[4][2][4];
#pragma unroll
    for (int mi = 0; mi < 4; mi++)
#pragma unroll
        for (int ni = 0; ni < 2; ni++)
#pragma unroll
            for (int r = 0; r < 4; r++) acc[mi][ni][r] = 0.f;

#pragma unroll
    for (int i = 0; i < 2; i++)
        cp16(smb + i * PL_B + frow * 80 + fc * 16, srcs[i] + (size_t)frow * DD + fc * 8);
    CP_COMMIT;

    for (int kt = 0; kt < 32; kt++) {
        if (kt < 31) {
#pragma unroll
            for (int i = 0; i < 2; i++)
                cp16(smb + ((kt + 1) & 1) * BUF1_B + i * PL_B + frow * 80 + fc * 16,
                     srcs[i] + (size_t)frow * DD + (kt + 1) * 32 + fc * 8);
            CP_COMMIT;
            CP_WAIT1;
        } else {
            CP_WAIT0;
        }
        __syncthreads();

        const uint32_t bufb = smb + (kt & 1) * BUF1_B;
#pragma unroll
        for (int ks = 0; ks < 2; ks++) {
            uint32_t a_h[4][4], b4[4], b_h[2][2];
#pragma unroll
            for (int mi = 0; mi < 4; mi++)
                ldsm4(a_h[mi][0], a_h[mi][1], a_h[mi][2], a_h[mi][3],
                      bufb + (wm + mi * 16 + lrow) * 80 + ks * 32 + lkh);
            ldsm4(b4[0], b4[1], b4[2], b4[3],
                  bufb + PL_B + (wn + lrow) * 80 + ks * 32 + lkh);
            b_h[0][0] = b4[0]; b_h[0][1] = b4[2];
            b_h[1][0] = b4[1]; b_h[1][1] = b4[3];
#pragma unroll
            for (int mi = 0; mi < 4; mi++)
#pragma unroll
                for (int ni = 0; ni < 2; ni++)
                    mma_f16(acc[mi][ni], a_h[mi], b_h[ni]);
        }
        __syncthreads();
    }

    if (outT) {
        __half* smT = (__half*)sm;
#pragma unroll
        for (int mi = 0; mi < 4; mi++) {
            int r = wm + mi * 16 + g;
            float nv0 = npm[bm + r] * scale, nv1 = npm[bm + r + 8] * scale;
#pragma unroll
            for (int ni = 0; ni < 2; ni++) {
                int c = wn + ni * 8 + 2 * tg;
                float b0 = bias[bn + c], b1 = bias[bn + c + 1];
                smT[c * 136 + r]           = __float2half((acc[mi][ni][0] + b0) * nv0);
                smT[(c + 1) * 136 + r]     = __float2half((acc[mi][ni][1] + b1) * nv0);
                smT[c * 136 + r + 8]       = __float2half((acc[mi][ni][2] + b0) * nv1);
                smT[(c + 1) * 136 + r + 8] = __float2half((acc[mi][ni][3] + b1) * nv1);
            }
        }
        __syncthreads();
        const int b = bm >> 10, token0 = bm & 1023;
#pragma unroll
        for (int p = 0; p < 4; p++) {
            int cr = (tid >> 4) + p * 32;
            int unit = tid & 15;
            int C = bn + cr;
            int h = C >> 6, d = C & 63;
            size_t dst = ((size_t)(b * 16 + h) * 64 + d) * 1024 + token0 + unit * 8;
            *(uint4*)&outT[dst] = *(const uint4*)&smT[cr * 136 + unit * 8];
        }
    } else if (outH) {
#pragma unroll
        for (int mi = 0; mi < 4; mi++) {
            int r0 = bm + wm + mi * 16 + g, r1 = r0 + 8;
            float nv0 = npm[r0] * scale, nv1 = npm[r1] * scale;
#pragma unroll
            for (int ni = 0; ni < 2; ni++) {
                int c0 = bn + wn + ni * 8 + 2 * tg;
                float b0 = bias[c0], b1 = bias[c0 + 1];
                *(__half2*)&outH[(size_t)r0 * DD + c0] =
                    __floats2half2_rn((acc[mi][ni][0] + b0) * nv0, (acc[mi][ni][1] + b1) * nv0);
                *(__half2*)&outH[(size_t)r1 * DD + c0] =
                    __floats2half2_rn((acc[mi][ni][2] + b0) * nv1, (acc[mi][ni][3] + b1) * nv1);
            }
        }
    } else {
#pragma unroll
        for (int mi = 0; mi < 4; mi++) {
            int r0 = bm + wm + mi * 16 + g, r1 = r0 + 8;
            float nv0 = npm[r0] * scale, nv1 = npm[r1] * scale;
#pragma unroll
            for (int ni = 0; ni < 2; ni++) {
                int c0 = bn + wn + ni * 8 + 2 * tg;
                float b0 = bias[c0], b1 = bias[c0 + 1];
                *(float2*)&outF[(size_t)r0 * DD + c0] =
                    make_float2((acc[mi][ni][0] + b0) * nv0, (acc[mi][ni][1] + b1) * nv0);
                *(float2*)&outF[(size_t)r1 * DD + c0] =
                    make_float2((acc[mi][ni][2] + b0) * nv1, (acc[mi][ni][3] + b1) * nv1);
            }
        }
    }
}

// ===========================================================================
// Fused attention (R11 structure): block = (b,h) x 32 q-rows, 512 threads
// S = QK^T fp16 (K quad-buffered, ldmatrix) -> 2-pass no-max softmax
// (mask folded into exp pass; P fp16 smem) -> PV fp16 mma (V^T quad-buffered)
// smem map: S f32 [0,131584) | Q @131584 (4608) | K 4x18432 @136192 = 209920
// overlays:  VT 4x17408 @0 (PV) | P 32x2096 @131584 (after S-phase)
// ===========================================================================
#define SSTR 1028
#define QOFF 131584
#define KOFF 136192
#define KBUF 18432
#define ATT_SMEM 209920
#define POFF QOFF
#define PSTRB 2096
#define VTSTRB 272
#define VTBUF 17408

__global__ __launch_bounds__(512) void attn_kernel(
    const __half* __restrict__ qh, const __half* __restrict__ kh,
    const __half* __restrict__ vhT, const int* __restrict__ mask,
    float* __restrict__ attn, __half* __restrict__ ctx)
{
    extern __shared__ char sm[];
    const uint32_t smb = smem_u32(sm);
    float* S = (float*)sm;

    const int tid = threadIdx.x, wid = tid >> 5, lane = tid & 31;
    const int g = lane >> 2, tg = lane & 3;
    const int lrow = lane & 15, lkh = (lane >> 4) * 16;
    const int bh = blockIdx.x;
    const int b = bh >> 4, h = bh & 15;
    const int q0 = blockIdx.y * 32;
    const int wq = wid & 1;
    const int wk = wid >> 1;

    const __half* qp_g = qh + ((size_t)b * LL + q0) * DD + h * DK;
    const __half* kp_g = kh + (size_t)b * LL * DD + h * DK;
    const __half* vTp = vhT + (size_t)bh * DK * LL;
    float* attnBase = attn + ((size_t)bh * LL + q0) * LL;

    // Q load + K0 (group 1), K1 (group 2)
    if (tid < 256) {
        int row = tid >> 3, c8 = tid & 7;
        cp16(smb + QOFF + row * 144 + c8 * 16, qp_g + (size_t)row * DD + c8 * 8);
    }
#pragma unroll
    for (int j = 0; j < 2; j++) {
        int idx = tid + 512 * j;
        int row = idx >> 3, c8 = idx & 7;
        cp16(smb + KOFF + row * 144 + c8 * 16, kp_g + (size_t)row * DD + c8 * 8);
    }
    CP_COMMIT;
#pragma unroll
    for (int j = 0; j < 2; j++) {
        int idx = tid + 512 * j;
        int row = idx >> 3, c8 = idx & 7;
        cp16(smb + KOFF + KBUF + row * 144 + c8 * 16,
             kp_g + (size_t)(128 + row) * DD + c8 * 8);
    }
    CP_COMMIT;

    // ---- S = Q K^T over 8 chunks, quad-buffered K ----
    for (int kc = 0; kc < 8; kc++) {
        if (kc < 6) {
#pragma unroll
            for (int j = 0; j < 2; j++) {
                int idx = tid + 512 * j;
                int row = idx >> 3, c8 = idx & 7;
                cp16(smb + KOFF + ((kc + 2) & 3) * KBUF + row * 144 + c8 * 16,
                     kp_g + (size_t)((kc + 2) * 128 + row) * DD + c8 * 8);
            }
            CP_COMMIT;
            CP_WAIT2;
        } else if (kc == 6) {
            CP_WAIT1;
        } else {
            CP_WAIT0;
        }
        __syncthreads();

        const uint32_t kb = smb + KOFF + (kc & 3) * KBUF;
        float sacc[2][4];
#pragma unroll
        for (int ni = 0; ni < 2; ni++)
#pragma unroll
            for (int r = 0; r < 4; r++) sacc[ni][r] = 0.f;

#pragma unroll
        for (int ks = 0; ks < 4; ks++) {
            uint32_t a_h[4], b4[4], b_h[2][2];
            ldsm4(a_h[0], a_h[1], a_h[2], a_h[3],
                  smb + QOFF + (wq * 16 + lrow) * 144 + ks * 32 + lkh);
            ldsm4(b4[0], b4[1], b4[2], b4[3],
                  kb + (wk * 16 + lrow) * 144 + ks * 32 + lkh);
            b_h[0][0] = b4[0]; b_h[0][1] = b4[2];
            b_h[1][0] = b4[1]; b_h[1][1] = b4[3];
            mma_f16(sacc[0], a_h, b_h[0]);
            mma_f16(sacc[1], a_h, b_h[1]);
        }
#pragma unroll
        for (int ni = 0; ni < 2; ni++) {
            int c = kc * 128 + wk * 16 + ni * 8 + 2 * tg;
            *(float2*)&S[(wq * 16 + g) * SSTR + c]     = make_float2(sacc[ni][0], sacc[ni][1]);
            *(float2*)&S[(wq * 16 + g + 8) * SSTR + c] = make_float2(sacc[ni][2], sacc[ni][3]);
        }
    }
    __syncthreads();

    // ---- 2-pass no-max softmax; mask folded into exp pass ----
#pragma unroll
    for (int rr = 0; rr < 2; rr++) {
        int r = wid * 2 + rr;
        float* Sr = S + r * SSTR;
        const int* mr = mask + ((size_t)b * LL + q0 + r) * LL;
        float sum = 0.f;
        for (int c = lane; c < 1024; c += 32) {
            float e = mr[c] ? 0.f : __expf(Sr[c]);
            Sr[c] = e;
            sum += e;
        }
#pragma unroll
        for (int o = 16; o; o >>= 1) sum += __shfl_xor_sync(0xffffffffu, sum, o);
        float inv = 1.f / sum;
        float* dst = attnBase + (size_t)r * LL;
        __half* Pr = (__half*)(sm + POFF + r * PSTRB);
        for (int c = lane; c < 1024; c += 32) {
            float p = Sr[c] * inv;
            dst[c] = p;
            Pr[c] = __float2half(p);
        }
    }
    __syncthreads();   // P complete; S region dead -> VT buffers

    // prefetch V^T chunks 0,1 (groups 1,2)
#pragma unroll
    for (int j = 0; j < 2; j++) {
        int idx = tid + 512 * j;
        int d = idx >> 4, tk = idx & 15;
        cp16(smb + d * VTSTRB + tk * 16, vTp + (size_t)d * LL + tk * 8);
    }
    CP_COMMIT;
#pragma unroll
    for (int j = 0; j < 2; j++) {
        int idx = tid + 512 * j;
        int d = idx >> 4, tk = idx & 15;
        cp16(smb + VTBUF + d * VTSTRB + tk * 16, vTp + (size_t)d * LL + 128 + tk * 8);
    }
    CP_COMMIT;

    // ---- PV: fp16 mma, warp tile 16q x 8d, quad-buffered V^T ----
    float pacc[4] = {0.f, 0.f, 0.f, 0.f};
    for (int vc = 0; vc < 8; vc++) {
        if (vc < 6) {
#pragma unroll
            for (int j = 0; j < 2; j++) {
                int idx = tid + 512 * j;
                int d = idx >> 4, tk = idx & 15;
                cp16(smb + ((vc + 2) & 3) * VTBUF + d * VTSTRB + tk * 16,
                     vTp + (size_t)d * LL + (vc + 2) * 128 + tk * 8);
            }
            CP_COMMIT;
            CP_WAIT2;
        } else if (vc == 6) {
            CP_WAIT1;
        } else {
            CP_WAIT0;
        }
        __syncthreads();

        const uint32_t vtb = smb + (vc & 3) * VTBUF;
        const uint32_t pb = smb + POFF + (wq * 16) * PSTRB + vc * 256;
#pragma unroll
        for (int kk = 0; kk < 8; kk++) {
            uint32_t a[4], bfr[2];
            ldsm4(a[0], a[1], a[2], a[3], pb + lrow * PSTRB + kk * 32 + lkh);
            ldsm2(bfr[0], bfr[1],
                  vtb + (wk * 8 + (lane & 7)) * VTSTRB + kk * 32 + ((lane >> 3) & 1) * 16);
            mma_f16(pacc, a, bfr);
        }
    }

    {
        int c = h * DK + wk * 8 + 2 * tg;
        size_t r0 = (size_t)b * LL + q0 + wq * 16 + g;
        *(__half2*)&ctx[r0 * DD + c]       = __floats2half2_rn(pacc[0], pacc[1]);
        *(__half2*)&ctx[(r0 + 8) * DD + c] = __floats2half2_rn(pacc[2], pacc[3]);
    }
}

// ---------------------------------------------------------------------------
// LayerNorm(proj + residual) * g + b
// ---------------------------------------------------------------------------
__global__ __launch_bounds__(256) void ln_kernel(
    const float* __restrict__ proj, const float* __restrict__ resid,
    const float* __restrict__ gam, const float* __restrict__ bet,
    float* __restrict__ out)
{
    __shared__ float red[8];
    const int row = blockIdx.x;
    const int tid = threadIdx.x;
    const int c0 = tid * 4;
    const int lane = tid & 31, wid = tid >> 5;

    float4 pv = *(const float4*)(proj + (size_t)row * DD + c0);
    float4 rv = *(const float4*)(resid + (size_t)row * DD + c0);
    float x0 = pv.x + rv.x, x1 = pv.y + rv.y, x2 = pv.z + rv.z, x3 = pv.w + rv.w;

    float s = x0 + x1 + x2 + x3;
#pragma unroll
    for (int o = 16; o; o >>= 1) s += __shfl_xor_sync(0xffffffffu, s, o);
    if (lane == 0) red[wid] = s;
    __syncthreads();
    float tot = (lane < 8) ? red[lane] : 0.f;
#pragma unroll
    for (int o = 4; o; o >>= 1) tot += __shfl_xor_sync(0xffffffffu, tot, o);
    tot = __shfl_sync(0xffffffffu, tot, 0);
    float mean = tot * (1.f / 1024.f);

    float d0 = x0 - mean, d1 = x1 - mean, d2 = x2 - mean, d3 = x3 - mean;
    float sq = d0 * d0 + d1 * d1 + d2 * d2 + d3 * d3;
#pragma unroll
    for (int o = 16; o; o >>= 1) sq += __shfl_xor_sync(0xffffffffu, sq, o);
    __syncthreads();
    if (lane == 0) red[wid] = sq;
    __syncthreads();
    float tot2 = (lane < 8) ? red[lane] : 0.f;
#pragma unroll
    for (int o = 4; o; o >>= 1) tot2 += __shfl_xor_sync(0xffffffffu, tot2, o);
    tot2 = __shfl_sync(0xffffffffu, tot2, 0);
    float k = rsqrtf(tot2 * (1.f / 1024.f) + 1e-5f);

    float4 gv = *(const float4*)(gam + c0);
    float4 bv = *(const float4*)(bet + c0);
    float4 ov;
    ov.x = d0 * k * gv.x + bv.x;
    ov.y = d1 * k * gv.y + bv.y;
    ov.z = d2 * k * gv.z + bv.z;
    ov.w = d3 * k * gv.w + bv.w;
    *(float4*)&out[(size_t)row * DD + c0] = ov;
}

// ---------------------------------------------------------------------------
extern "C" void kernel_launch(void* const* d_in, const int* in_sizes, int n_in,
                              void* d_out, int out_size)
{
    const float* q    = (const float*)d_in[0];
    const float* k    = (const float*)d_in[1];
    const float* v    = (const float*)d_in[2];
    const int*   mask = (const int*)  d_in[3];
    const float* npm  = (const float*)d_in[4];
    const float* Wq   = (const float*)d_in[5];
    const float* bq   = (const float*)d_in[6];
    const float* Wk   = (const float*)d_in[7];
    const float* bk   = (const float*)d_in[8];
    const float* Wv   = (const float*)d_in[9];
    const float* bv   = (const float*)d_in[10];
    const float* Wf   = (const float*)d_in[11];
    const float* bf   = (const float*)d_in[12];
    const float* ln_g = (const float*)d_in[13];
    const float* ln_b = (const float*)d_in[14];

    float* out  = (float*)d_out;
    float* attn = out + (size_t)BB * LL * DD;

    __half *qh, *kh, *vhT, *ctx, *as, *ws;
    float *proj;
    cudaGetSymbolAddress((void**)&qh,  g_qh);
    cudaGetSymbolAddress((void**)&kh,  g_kh);
    cudaGetSymbolAddress((void**)&vhT, g_vhT);
    cudaGetSymbolAddress((void**)&ctx, g_ctx);
    cudaGetSymbolAddress((void**)&proj, g_proj);
    cudaGetSymbolAddress((void**)&as,  g_as);
    cudaGetSymbolAddress((void**)&ws,  g_ws);

    cudaFuncSetAttribute(gemm_f16_1t, cudaFuncAttributeMaxDynamicSharedMemorySize, GEMM1_SMEM);
    cudaFuncSetAttribute(attn_kernel, cudaFuncAttributeMaxDynamicSharedMemorySize, ATT_SMEM);

    const int nA4 = ROWS_TOT * DD / 4;
    const int nW4 = DD * DD / 4;
    dim3 gG(DD / 128, ROWS_TOT / 128);   // (8, 64)

    // Q projection (scale 1/8 folded) -> fp16
    conv_f16<<<(nA4 + 255) / 256, 256>>>(q, as, nA4);
    conv_f16<<<(nW4 + 255) / 256, 256>>>(Wq, ws, nW4);
    gemm_f16_1t<<<gG, 512, GEMM1_SMEM>>>(as, ws, bq, npm, 0.125f, nullptr, qh, nullptr);
    // K projection -> fp16
    conv_f16<<<(nA4 + 255) / 256, 256>>>(k, as, nA4);
    conv_f16<<<(nW4 + 255) / 256, 256>>>(Wk, ws, nW4);
    gemm_f16_1t<<<gG, 512, GEMM1_SMEM>>>(as, ws, bk, npm, 1.0f, nullptr, kh, nullptr);
    // V projection -> transposed fp16 vhT
    conv_f16<<<(nA4 + 255) / 256, 256>>>(v, as, nA4);
    conv_f16<<<(nW4 + 255) / 256, 256>>>(Wv, ws, nW4);
    gemm_f16_1t<<<gG, 512, GEMM1_SMEM>>>(as, ws, bv, npm, 1.0f, nullptr, nullptr, vhT);

    // Fused attention (ctx out as fp16)
    attn_kernel<<<dim3(BB * HH, LL / 32), 512, ATT_SMEM>>>(
        qh, kh, vhT, mask, attn, ctx);

    // Output projection (ctx fp16 direct) -> fp32, then LN
    conv_f16<<<(nW4 + 255) / 256, 256>>>(Wf, ws, nW4);
    gemm_f16_1t<<<gG, 512, GEMM1_SMEM>>>(ctx, ws, bf, npm, 1.0f, proj, nullptr, nullptr);

    ln_kernel<<<ROWS_TOT, 256>>>(proj, q, ln_g, ln_b, out);
}

// round 15
// speedup vs baseline: 1.6832x; 1.1730x over previous
#include <cuda_runtime.h>
#include <cuda_fp16.h>
#include <math.h>
#include <cstdint>

#define BB 8
#define LL 1024
#define DD 1024
#define HH 16
#define DK 64
#define ROWS_TOT (BB*LL)          // 8192

// Scratch (device globals)
__device__ __half g_qh [(size_t)ROWS_TOT * DD];   // fp16 q heads (scaled 1/8)
__device__ __half g_kh [(size_t)ROWS_TOT * DD];   // fp16 k heads
__device__ __half g_vhT[(size_t)ROWS_TOT * DD];   // [b][h][d][token] fp16
__device__ __half g_ctx[(size_t)ROWS_TOT * DD];   // fp16
__device__ float  g_proj[(size_t)ROWS_TOT * DD];
__device__ __half g_as [(size_t)ROWS_TOT * DD];
__device__ __half g_ws [(size_t)DD * DD];

// ---------------------------------------------------------------------------
// helpers
// ---------------------------------------------------------------------------
__device__ __forceinline__ uint32_t smem_u32(const void* p) {
    uint32_t a;
    asm("{ .reg .u64 t; cvta.to.shared.u64 t, %1; cvt.u32.u64 %0, t; }" : "=r"(a) : "l"(p));
    return a;
}
__device__ __forceinline__ void cp16(uint32_t dst, const void* src) {
    asm volatile("cp.async.cg.shared.global [%0], [%1], 16;" :: "r"(dst), "l"(src));
}
#define CP_COMMIT asm volatile("cp.async.commit_group;" ::: "memory")
#define CP_WAIT2  asm volatile("cp.async.wait_group 2;" ::: "memory")
#define CP_WAIT1  asm volatile("cp.async.wait_group 1;" ::: "memory")
#define CP_WAIT0  asm volatile("cp.async.wait_group 0;" ::: "memory")

__device__ __forceinline__ void mma_f16(float* c, const uint32_t* a, const uint32_t* b) {
    asm volatile(
        "mma.sync.aligned.m16n8k16.row.col.f32.f16.f16.f32 "
        "{%0,%1,%2,%3},{%4,%5,%6,%7},{%8,%9},{%0,%1,%2,%3};"
        : "+f"(c[0]), "+f"(c[1]), "+f"(c[2]), "+f"(c[3])
        : "r"(a[0]), "r"(a[1]), "r"(a[2]), "r"(a[3]), "r"(b[0]), "r"(b[1]));
}
__device__ __forceinline__ void ldsm4(uint32_t& r0, uint32_t& r1, uint32_t& r2,
                                      uint32_t& r3, uint32_t addr) {
    asm volatile("ldmatrix.sync.aligned.m8n8.x4.shared.b16 {%0,%1,%2,%3}, [%4];"
                 : "=r"(r0), "=r"(r1), "=r"(r2), "=r"(r3) : "r"(addr));
}
__device__ __forceinline__ void ldsm2(uint32_t& r0, uint32_t& r1, uint32_t addr) {
    asm volatile("ldmatrix.sync.aligned.m8n8.x2.shared.b16 {%0,%1}, [%2];"
                 : "=r"(r0), "=r"(r1) : "r"(addr));
}

// f32 -> fp16 convert
__global__ __launch_bounds__(256) void conv_f16(
    const float* __restrict__ x, __half* __restrict__ hi, int n4)
{
    int i = blockIdx.x * blockDim.x + threadIdx.x;
    if (i >= n4) return;
    float4 v = ((const float4*)x)[i];
    ((__half2*)hi)[i * 2]     = __floats2half2_rn(v.x, v.y);
    ((__half2*)hi)[i * 2 + 1] = __floats2half2_rn(v.z, v.w);
}

// ===========================================================================
// single-term fp16 GEMM (R14, proven). Output modes:
//   outT: transposed fp16 (V proj -> vhT) | outH: planar fp16 (Q/K) | outF: fp32
// 128x128 tile, BK=32, 512 threads
// ===========================================================================
#define PL_E 5120
#define PL_B (PL_E*2)
#define BUF1_B (2*PL_B)
#define GEMM1_SMEM (2*BUF1_B)

__global__ __launch_bounds__(512) void gemm_f16_1t(
    const __half* __restrict__ A, const __half* __restrict__ B,
    const float* __restrict__ bias, const float* __restrict__ npm, float scale,
    float* __restrict__ outF, __half* __restrict__ outH, __half* __restrict__ outT)
{
    extern __shared__ char sm[];
    const uint32_t smb = smem_u32(sm);
    const int tid = threadIdx.x, wid = tid >> 5, lane = tid & 31;
    const int g = lane >> 2, tg = lane & 3;
    const int bm = blockIdx.y * 128, bn = blockIdx.x * 128;
    const int wm = (wid & 1) * 64, wn = (wid >> 1) * 16;
    const int lrow = lane & 15, lkh = (lane >> 4) * 16;

    const __half* srcs[2] = { A + (size_t)bm * DD, B + (size_t)bn * DD };
    const int frow = tid >> 2, fc = tid & 3;

    float acc[4][2][4];
#pragma unroll
    for (int mi = 0; mi < 4; mi++)
#pragma unroll
        for (int ni = 0; ni < 2; ni++)
#pragma unroll
            for (int r = 0; r < 4; r++) acc[mi][ni][r] = 0.f;

#pragma unroll
    for (int i = 0; i < 2; i++)
        cp16(smb + i * PL_B + frow * 80 + fc * 16, srcs[i] + (size_t)frow * DD + fc * 8);
    CP_COMMIT;

    for (int kt = 0; kt < 32; kt++) {
        if (kt < 31) {
#pragma unroll
            for (int i = 0; i < 2; i++)
                cp16(smb + ((kt + 1) & 1) * BUF1_B + i * PL_B + frow * 80 + fc * 16,
                     srcs[i] + (size_t)frow * DD + (kt + 1) * 32 + fc * 8);
            CP_COMMIT;
            CP_WAIT1;
        } else {
            CP_WAIT0;
        }
        __syncthreads();

        const uint32_t bufb = smb + (kt & 1) * BUF1_B;
#pragma unroll
        for (int ks = 0; ks < 2; ks++) {
            uint32_t a_h[4][4], b4[4], b_h[2][2];
#pragma unroll
            for (int mi = 0; mi < 4; mi++)
                ldsm4(a_h[mi][0], a_h[mi][1], a_h[mi][2], a_h[mi][3],
                      bufb + (wm + mi * 16 + lrow) * 80 + ks * 32 + lkh);
            ldsm4(b4[0], b4[1], b4[2], b4[3],
                  bufb + PL_B + (wn + lrow) * 80 + ks * 32 + lkh);
            b_h[0][0] = b4[0]; b_h[0][1] = b4[2];
            b_h[1][0] = b4[1]; b_h[1][1] = b4[3];
#pragma unroll
            for (int mi = 0; mi < 4; mi++)
#pragma unroll
                for (int ni = 0; ni < 2; ni++)
                    mma_f16(acc[mi][ni], a_h[mi], b_h[ni]);
        }
        __syncthreads();
    }

    if (outT) {
        __half* smT = (__half*)sm;
#pragma unroll
        for (int mi = 0; mi < 4; mi++) {
            int r = wm + mi * 16 + g;
            float nv0 = npm[bm + r] * scale, nv1 = npm[bm + r + 8] * scale;
#pragma unroll
            for (int ni = 0; ni < 2; ni++) {
                int c = wn + ni * 8 + 2 * tg;
                float b0 = bias[bn + c], b1 = bias[bn + c + 1];
                smT[c * 136 + r]           = __float2half((acc[mi][ni][0] + b0) * nv0);
                smT[(c + 1) * 136 + r]     = __float2half((acc[mi][ni][1] + b1) * nv0);
                smT[c * 136 + r + 8]       = __float2half((acc[mi][ni][2] + b0) * nv1);
                smT[(c + 1) * 136 + r + 8] = __float2half((acc[mi][ni][3] + b1) * nv1);
            }
        }
        __syncthreads();
        const int b = bm >> 10, token0 = bm & 1023;
#pragma unroll
        for (int p = 0; p < 4; p++) {
            int cr = (tid >> 4) + p * 32;
            int unit = tid & 15;
            int C = bn + cr;
            int h = C >> 6, d = C & 63;
            size_t dst = ((size_t)(b * 16 + h) * 64 + d) * 1024 + token0 + unit * 8;
            *(uint4*)&outT[dst] = *(const uint4*)&smT[cr * 136 + unit * 8];
        }
    } else if (outH) {
#pragma unroll
        for (int mi = 0; mi < 4; mi++) {
            int r0 = bm + wm + mi * 16 + g, r1 = r0 + 8;
            float nv0 = npm[r0] * scale, nv1 = npm[r1] * scale;
#pragma unroll
            for (int ni = 0; ni < 2; ni++) {
                int c0 = bn + wn + ni * 8 + 2 * tg;
                float b0 = bias[c0], b1 = bias[c0 + 1];
                *(__half2*)&outH[(size_t)r0 * DD + c0] =
                    __floats2half2_rn((acc[mi][ni][0] + b0) * nv0, (acc[mi][ni][1] + b1) * nv0);
                *(__half2*)&outH[(size_t)r1 * DD + c0] =
                    __floats2half2_rn((acc[mi][ni][2] + b0) * nv1, (acc[mi][ni][3] + b1) * nv1);
            }
        }
    } else {
#pragma unroll
        for (int mi = 0; mi < 4; mi++) {
            int r0 = bm + wm + mi * 16 + g, r1 = r0 + 8;
            float nv0 = npm[r0] * scale, nv1 = npm[r1] * scale;
#pragma unroll
            for (int ni = 0; ni < 2; ni++) {
                int c0 = bn + wn + ni * 8 + 2 * tg;
                float b0 = bias[c0], b1 = bias[c0 + 1];
                *(float2*)&outF[(size_t)r0 * DD + c0] =
                    make_float2((acc[mi][ni][0] + b0) * nv0, (acc[mi][ni][1] + b1) * nv0);
                *(float2*)&outF[(size_t)r1 * DD + c0] =
                    make_float2((acc[mi][ni][2] + b0) * nv1, (acc[mi][ni][3] + b1) * nv1);
            }
        }
    }
}

// ===========================================================================
// Fused attention, fused-exp variant: block = (b,h) x 32 q-rows, 512 threads
// S-phase: QK^T mma -> mask (smem-staged) -> e = exp(s)*2^-4 -> P fp16 smem
// (unnormalized) + fp32 row-sum accumulation in regs.
// Reduce sums (tg shfl + 32x8 smem) -> inv per row.
// attn = P * inv (one smem read pass). PV on unnormalized P; ctx *= inv.
// smem: P 67072 @0 | red 1024 @67072 | invs 128 @68096 | Q 4608 @68224 |
//       K 4x18432 @72832 | mask 4x16896 @146560  => 214144 total
// PV overlay: VT 4x17408 @72832 (inside K region)
// ===========================================================================
#define POFF 0
#define PSTRB 2096
#define REDOFF 67072
#define INVOFF 68096
#define QOFF 68224
#define KOFF 72832
#define KBUF 18432
#define MOFF 146560
#define MBUF 16896
#define MSTR 528
#define VTBUF 17408
#define VTSTRB 272
#define ATT_SMEM 214144

__global__ __launch_bounds__(512) void attn_kernel(
    const __half* __restrict__ qh, const __half* __restrict__ kh,
    const __half* __restrict__ vhT, const int* __restrict__ mask,
    float* __restrict__ attn, __half* __restrict__ ctx)
{
    extern __shared__ char sm[];
    const uint32_t smb = smem_u32(sm);
    float* red = (float*)(sm + REDOFF);
    float* invs = (float*)(sm + INVOFF);

    const int tid = threadIdx.x, wid = tid >> 5, lane = tid & 31;
    const int g = lane >> 2, tg = lane & 3;
    const int lrow = lane & 15, lkh = (lane >> 4) * 16;
    const int bh = blockIdx.x;
    const int b = bh >> 4, h = bh & 15;
    const int q0 = blockIdx.y * 32;
    const int wq = wid & 1;
    const int wk = wid >> 1;
    const int row0 = wq * 16 + g;

    const __half* qp_g = qh + ((size_t)b * LL + q0) * DD + h * DK;
    const __half* kp_g = kh + (size_t)b * LL * DD + h * DK;
    const int* mp_g = mask + ((size_t)b * LL + q0) * LL;
    const __half* vTp = vhT + (size_t)bh * DK * LL;
    float* attnBase = attn + ((size_t)bh * LL + q0) * LL;

    // mask fill indices: 1024 cp16 per chunk (32 rows x 32 int4-groups)
    const int mrow = tid >> 5 << 1;        // rows tid/32*2 .. +1 handled via j
    // simpler: idx-based below

    // Q load + {K0,M0} (group 1), {K1,M1} (group 2)
    if (tid < 256) {
        int row = tid >> 3, c8 = tid & 7;
        cp16(smb + QOFF + row * 144 + c8 * 16, qp_g + (size_t)row * DD + c8 * 8);
    }
#pragma unroll
    for (int j = 0; j < 2; j++) {
        int idx = tid + 512 * j;
        int row = idx >> 3, c8 = idx & 7;
        cp16(smb + KOFF + row * 144 + c8 * 16, kp_g + (size_t)row * DD + c8 * 8);
        int mr = idx >> 5, mc = idx & 31;
        cp16(smb + MOFF + mr * MSTR + mc * 16, mp_g + (size_t)mr * LL + mc * 4);
    }
    CP_COMMIT;
#pragma unroll
    for (int j = 0; j < 2; j++) {
        int idx = tid + 512 * j;
        int row = idx >> 3, c8 = idx & 7;
        cp16(smb + KOFF + KBUF + row * 144 + c8 * 16,
             kp_g + (size_t)(128 + row) * DD + c8 * 8);
        int mr = idx >> 5, mc = idx & 31;
        cp16(smb + MOFF + MBUF + mr * MSTR + mc * 16,
             mp_g + (size_t)mr * LL + 128 + mc * 4);
    }
    CP_COMMIT;

    // ---- S-phase with fused exp: P unnormalized fp16, sums in regs ----
    float psum0 = 0.f, psum1 = 0.f;
    for (int kc = 0; kc < 8; kc++) {
        if (kc < 6) {
#pragma unroll
            for (int j = 0; j < 2; j++) {
                int idx = tid + 512 * j;
                int row = idx >> 3, c8 = idx & 7;
                cp16(smb + KOFF + ((kc + 2) & 3) * KBUF + row * 144 + c8 * 16,
                     kp_g + (size_t)((kc + 2) * 128 + row) * DD + c8 * 8);
                int mr = idx >> 5, mc = idx & 31;
                cp16(smb + MOFF + ((kc + 2) & 3) * MBUF + mr * MSTR + mc * 16,
                     mp_g + (size_t)mr * LL + (kc + 2) * 128 + mc * 4);
            }
            CP_COMMIT;
            CP_WAIT2;
        } else if (kc == 6) {
            CP_WAIT1;
        } else {
            CP_WAIT0;
        }
        __syncthreads();

        const uint32_t kb = smb + KOFF + (kc & 3) * KBUF;
        const char* mb = sm + MOFF + (kc & 3) * MBUF;
        float sacc[2][4];
#pragma unroll
        for (int ni = 0; ni < 2; ni++)
#pragma unroll
            for (int r = 0; r < 4; r++) sacc[ni][r] = 0.f;

#pragma unroll
        for (int ks = 0; ks < 4; ks++) {
            uint32_t a_h[4], b4[4], b_h[2][2];
            ldsm4(a_h[0], a_h[1], a_h[2], a_h[3],
                  smb + QOFF + (wq * 16 + lrow) * 144 + ks * 32 + lkh);
            ldsm4(b4[0], b4[1], b4[2], b4[3],
                  kb + (wk * 16 + lrow) * 144 + ks * 32 + lkh);
            b_h[0][0] = b4[0]; b_h[0][1] = b4[2];
            b_h[1][0] = b4[1]; b_h[1][1] = b4[3];
            mma_f16(sacc[0], a_h, b_h[0]);
            mma_f16(sacc[1], a_h, b_h[1]);
        }
        // mask + exp + store unnormalized P fp16 + accumulate sums
#pragma unroll
        for (int ni = 0; ni < 2; ni++) {
            int cl = wk * 16 + ni * 8 + 2 * tg;        // local col 0..127
            int2 m0 = *(const int2*)(mb + row0 * MSTR + cl * 4);
            int2 m1 = *(const int2*)(mb + (row0 + 8) * MSTR + cl * 4);
            float e0 = m0.x ? 0.f : __expf(sacc[ni][0]) * 0.0625f;
            float e1 = m0.y ? 0.f : __expf(sacc[ni][1]) * 0.0625f;
            float e2 = m1.x ? 0.f : __expf(sacc[ni][2]) * 0.0625f;
            float e3 = m1.y ? 0.f : __expf(sacc[ni][3]) * 0.0625f;
            psum0 += e0 + e1;
            psum1 += e2 + e3;
            int c = kc * 128 + cl;
            *(__half2*)(sm + POFF + row0 * PSTRB + c * 2)       = __floats2half2_rn(e0, e1);
            *(__half2*)(sm + POFF + (row0 + 8) * PSTRB + c * 2) = __floats2half2_rn(e2, e3);
        }
    }

    // ---- reduce row sums: tg shuffle then across 8 wk warps ----
    psum0 += __shfl_xor_sync(0xffffffffu, psum0, 1);
    psum0 += __shfl_xor_sync(0xffffffffu, psum0, 2);
    psum1 += __shfl_xor_sync(0xffffffffu, psum1, 1);
    psum1 += __shfl_xor_sync(0xffffffffu, psum1, 2);
    if (tg == 0) {
        red[row0 * 8 + wk] = psum0;
        red[(row0 + 8) * 8 + wk] = psum1;
    }
    __syncthreads();
    if (wk == 0 && tg == 0) {
        float s0 = 0.f, s1 = 0.f;
#pragma unroll
        for (int w = 0; w < 8; w++) {
            s0 += red[row0 * 8 + w];
            s1 += red[(row0 + 8) * 8 + w];
        }
        invs[row0] = 1.f / s0;
        invs[row0 + 8] = 1.f / s1;
    }
    __syncthreads();   // P + invs complete; K/mask regions dead -> VT

    // prefetch V^T chunks 0,1 (groups 1,2) into K region
#pragma unroll
    for (int j = 0; j < 2; j++) {
        int idx = tid + 512 * j;
        int d = idx >> 4, tk = idx & 15;
        cp16(smb + KOFF + d * VTSTRB + tk * 16, vTp + (size_t)d * LL + tk * 8);
    }
    CP_COMMIT;
#pragma unroll
    for (int j = 0; j < 2; j++) {
        int idx = tid + 512 * j;
        int d = idx >> 4, tk = idx & 15;
        cp16(smb + KOFF + VTBUF + d * VTSTRB + tk * 16,
             vTp + (size_t)d * LL + 128 + tk * 8);
    }
    CP_COMMIT;

    // ---- attn write: read P, scale by inv, coalesced fp32 store ----
#pragma unroll
    for (int rr = 0; rr < 2; rr++) {
        int r = wid * 2 + rr;
        float inv = invs[r];
        const __half2* Pr = (const __half2*)(sm + POFF + r * PSTRB);
        float* dst = attnBase + (size_t)r * LL;
#pragma unroll 4
        for (int c2 = lane; c2 < 512; c2 += 32) {
            float2 p2 = __half22float2(Pr[c2]);
            *(float2*)&dst[c2 * 2] = make_float2(p2.x * inv, p2.y * inv);
        }
    }

    // ---- PV on unnormalized P; scale ctx by inv in epilogue ----
    float pacc[4] = {0.f, 0.f, 0.f, 0.f};
    for (int vc = 0; vc < 8; vc++) {
        if (vc < 6) {
#pragma unroll
            for (int j = 0; j < 2; j++) {
                int idx = tid + 512 * j;
                int d = idx >> 4, tk = idx & 15;
                cp16(smb + KOFF + ((vc + 2) & 3) * VTBUF + d * VTSTRB + tk * 16,
                     vTp + (size_t)d * LL + (vc + 2) * 128 + tk * 8);
            }
            CP_COMMIT;
            CP_WAIT2;
        } else if (vc == 6) {
            CP_WAIT1;
        } else {
            CP_WAIT0;
        }
        __syncthreads();

        const uint32_t vtb = smb + KOFF + (vc & 3) * VTBUF;
        const uint32_t pb = smb + POFF + (wq * 16) * PSTRB + vc * 256;
#pragma unroll
        for (int kk = 0; kk < 8; kk++) {
            uint32_t a[4], bfr[2];
            ldsm4(a[0], a[1], a[2], a[3], pb + lrow * PSTRB + kk * 32 + lkh);
            ldsm2(bfr[0], bfr[1],
                  vtb + (wk * 8 + (lane & 7)) * VTSTRB + kk * 32 + ((lane >> 3) & 1) * 16);
            mma_f16(pacc, a, bfr);
        }
    }

    {
        float inv0 = invs[row0], inv1 = invs[row0 + 8];
        int c = h * DK + wk * 8 + 2 * tg;
        size_t r0 = (size_t)b * LL + q0 + row0;
        *(__half2*)&ctx[r0 * DD + c] =
            __floats2half2_rn(pacc[0] * inv0, pacc[1] * inv0);
        *(__half2*)&ctx[(r0 + 8) * DD + c] =
            __floats2half2_rn(pacc[2] * inv1, pacc[3] * inv1);
    }
}

// ---------------------------------------------------------------------------
// LayerNorm(proj + residual) * g + b
// ---------------------------------------------------------------------------
__global__ __launch_bounds__(256) void ln_kernel(
    const float* __restrict__ proj, const float* __restrict__ resid,
    const float* __restrict__ gam, const float* __restrict__ bet,
    float* __restrict__ out)
{
    __shared__ float red[8];
    const int row = blockIdx.x;
    const int tid = threadIdx.x;
    const int c0 = tid * 4;
    const int lane = tid & 31, wid = tid >> 5;

    float4 pv = *(const float4*)(proj + (size_t)row * DD + c0);
    float4 rv = *(const float4*)(resid + (size_t)row * DD + c0);
    float x0 = pv.x + rv.x, x1 = pv.y + rv.y, x2 = pv.z + rv.z, x3 = pv.w + rv.w;

    float s = x0 + x1 + x2 + x3;
#pragma unroll
    for (int o = 16; o; o >>= 1) s += __shfl_xor_sync(0xffffffffu, s, o);
    if (lane == 0) red[wid] = s;
    __syncthreads();
    float tot = (lane < 8) ? red[lane] : 0.f;
#pragma unroll
    for (int o = 4; o; o >>= 1) tot += __shfl_xor_sync(0xffffffffu, tot, o);
    tot = __shfl_sync(0xffffffffu, tot, 0);
    float mean = tot * (1.f / 1024.f);

    float d0 = x0 - mean, d1 = x1 - mean, d2 = x2 - mean, d3 = x3 - mean;
    float sq = d0 * d0 + d1 * d1 + d2 * d2 + d3 * d3;
#pragma unroll
    for (int o = 16; o; o >>= 1) sq += __shfl_xor_sync(0xffffffffu, sq, o);
    __syncthreads();
    if (lane == 0) red[wid] = sq;
    __syncthreads();
    float tot2 = (lane < 8) ? red[lane] : 0.f;
#pragma unroll
    for (int o = 4; o; o >>= 1) tot2 += __shfl_xor_sync(0xffffffffu, tot2, o);
    tot2 = __shfl_sync(0xffffffffu, tot2, 0);
    float k = rsqrtf(tot2 * (1.f / 1024.f) + 1e-5f);

    float4 gv = *(const float4*)(gam + c0);
    float4 bv = *(const float4*)(bet + c0);
    float4 ov;
    ov.x = d0 * k * gv.x + bv.x;
    ov.y = d1 * k * gv.y + bv.y;
    ov.z = d2 * k * gv.z + bv.z;
    ov.w = d3 * k * gv.w + bv.w;
    *(float4*)&out[(size_t)row * DD + c0] = ov;
}

// ---------------------------------------------------------------------------
extern "C" void kernel_launch(void* const* d_in, const int* in_sizes, int n_in,
                              void* d_out, int out_size)
{
    const float* q    = (const float*)d_in[0];
    const float* k    = (const float*)d_in[1];
    const float* v    = (const float*)d_in[2];
    const int*   mask = (const int*)  d_in[3];
    const float* npm  = (const float*)d_in[4];
    const float* Wq   = (const float*)d_in[5];
    const float* bq   = (const float*)d_in[6];
    const float* Wk   = (const float*)d_in[7];
    const float* bk   = (const float*)d_in[8];
    const float* Wv   = (const float*)d_in[9];
    const float* bv   = (const float*)d_in[10];
    const float* Wf   = (const float*)d_in[11];
    const float* bf   = (const float*)d_in[12];
    const float* ln_g = (const float*)d_in[13];
    const float* ln_b = (const float*)d_in[14];

    float* out  = (float*)d_out;
    float* attn = out + (size_t)BB * LL * DD;

    __half *qh, *kh, *vhT, *ctx, *as, *ws;
    float *proj;
    cudaGetSymbolAddress((void**)&qh,  g_qh);
    cudaGetSymbolAddress((void**)&kh,  g_kh);
    cudaGetSymbolAddress((void**)&vhT, g_vhT);
    cudaGetSymbolAddress((void**)&ctx, g_ctx);
    cudaGetSymbolAddress((void**)&proj, g_proj);
    cudaGetSymbolAddress((void**)&as,  g_as);
    cudaGetSymbolAddress((void**)&ws,  g_ws);

    cudaFuncSetAttribute(gemm_f16_1t, cudaFuncAttributeMaxDynamicSharedMemorySize, GEMM1_SMEM);
    cudaFuncSetAttribute(attn_kernel, cudaFuncAttributeMaxDynamicSharedMemorySize, ATT_SMEM);

    const int nA4 = ROWS_TOT * DD / 4;
    const int nW4 = DD * DD / 4;
    dim3 gG(DD / 128, ROWS_TOT / 128);   // (8, 64)

    // Q projection (scale 1/8 folded) -> fp16
    conv_f16<<<(nA4 + 255) / 256, 256>>>(q, as, nA4);
    conv_f16<<<(nW4 + 255) / 256, 256>>>(Wq, ws, nW4);
    gemm_f16_1t<<<gG, 512, GEMM1_SMEM>>>(as, ws, bq, npm, 0.125f, nullptr, qh, nullptr);
    // K projection -> fp16
    conv_f16<<<(nA4 + 255) / 256, 256>>>(k, as, nA4);
    conv_f16<<<(nW4 + 255) / 256, 256>>>(Wk, ws, nW4);
    gemm_f16_1t<<<gG, 512, GEMM1_SMEM>>>(as, ws, bk, npm, 1.0f, nullptr, kh, nullptr);
    // V projection -> transposed fp16 vhT
    conv_f16<<<(nA4 + 255) / 256, 256>>>(v, as, nA4);
    conv_f16<<<(nW4 + 255) / 256, 256>>>(Wv, ws, nW4);
    gemm_f16_1t<<<gG, 512, GEMM1_SMEM>>>(as, ws, bv, npm, 1.0f, nullptr, nullptr, vhT);

    // Fused attention (ctx out as fp16)
    attn_kernel<<<dim3(BB * HH, LL / 32), 512, ATT_SMEM>>>(
        qh, kh, vhT, mask, attn, ctx);

    // Output projection (ctx fp16 direct) -> fp32, then LN
    conv_f16<<<(nW4 + 255) / 256, 256>>>(Wf, ws, nW4);
    gemm_f16_1t<<<gG, 512, GEMM1_SMEM>>>(ctx, ws, bf, npm, 1.0f, proj, nullptr, nullptr);

    ln_kernel<<<ROWS_TOT, 256>>>(proj, q, ln_g, ln_b, out);
}

// round 16
// speedup vs baseline: 1.8913x; 1.1236x over previous
#include <cuda_runtime.h>
#include <cuda_fp16.h>
#include <math.h>
#include <cstdint>

#define BB 8
#define LL 1024
#define DD 1024
#define HH 16
#define DK 64
#define ROWS_TOT (BB*LL)          // 8192

// Scratch (device globals)
__device__ __half g_qh [(size_t)ROWS_TOT * DD];   // fp16 q heads (scaled 1/8)
__device__ __half g_kh [(size_t)ROWS_TOT * DD];   // fp16 k heads
__device__ __half g_vhT[(size_t)ROWS_TOT * DD];   // [b][h][d][token] fp16
__device__ __half g_ctx[(size_t)ROWS_TOT * DD];   // fp16
__device__ float  g_proj[(size_t)ROWS_TOT * DD];
__device__ __half g_as [(size_t)ROWS_TOT * DD];
__device__ __half g_ws [(size_t)DD * DD];
__device__ uint8_t g_mb[(size_t)BB * LL * LL];    // byte mask

// ---------------------------------------------------------------------------
// helpers
// ---------------------------------------------------------------------------
__device__ __forceinline__ uint32_t smem_u32(const void* p) {
    uint32_t a;
    asm("{ .reg .u64 t; cvta.to.shared.u64 t, %1; cvt.u32.u64 %0, t; }" : "=r"(a) : "l"(p));
    return a;
}
__device__ __forceinline__ void cp16(uint32_t dst, const void* src) {
    asm volatile("cp.async.cg.shared.global [%0], [%1], 16;" :: "r"(dst), "l"(src));
}
#define CP_COMMIT asm volatile("cp.async.commit_group;" ::: "memory")
#define CP_WAIT1  asm volatile("cp.async.wait_group 1;" ::: "memory")
#define CP_WAIT0  asm volatile("cp.async.wait_group 0;" ::: "memory")

__device__ __forceinline__ void mma_f16(float* c, const uint32_t* a, const uint32_t* b) {
    asm volatile(
        "mma.sync.aligned.m16n8k16.row.col.f32.f16.f16.f32 "
        "{%0,%1,%2,%3},{%4,%5,%6,%7},{%8,%9},{%0,%1,%2,%3};"
        : "+f"(c[0]), "+f"(c[1]), "+f"(c[2]), "+f"(c[3])
        : "r"(a[0]), "r"(a[1]), "r"(a[2]), "r"(a[3]), "r"(b[0]), "r"(b[1]));
}
__device__ __forceinline__ void ldsm4(uint32_t& r0, uint32_t& r1, uint32_t& r2,
                                      uint32_t& r3, uint32_t addr) {
    asm volatile("ldmatrix.sync.aligned.m8n8.x4.shared.b16 {%0,%1,%2,%3}, [%4];"
                 : "=r"(r0), "=r"(r1), "=r"(r2), "=r"(r3) : "r"(addr));
}

// f32 -> fp16 convert
__global__ __launch_bounds__(256) void conv_f16(
    const float* __restrict__ x, __half* __restrict__ hi, int n4)
{
    int i = blockIdx.x * blockDim.x + threadIdx.x;
    if (i >= n4) return;
    float4 v = ((const float4*)x)[i];
    ((__half2*)hi)[i * 2]     = __floats2half2_rn(v.x, v.y);
    ((__half2*)hi)[i * 2 + 1] = __floats2half2_rn(v.z, v.w);
}

// int32 mask -> uint8 mask
__global__ __launch_bounds__(256) void mask_byte(
    const int* __restrict__ m, uint8_t* __restrict__ mb, int n4)
{
    int i = blockIdx.x * blockDim.x + threadIdx.x;
    if (i >= n4) return;
    int4 v = ((const int4*)m)[i];
    uchar4 o;
    o.x = v.x ? 1 : 0; o.y = v.y ? 1 : 0;
    o.z = v.z ? 1 : 0; o.w = v.w ? 1 : 0;
    ((uchar4*)mb)[i] = o;
}

// ===========================================================================
// single-term fp16 GEMM (R14, proven). Output modes:
//   outT: transposed fp16 (V proj -> vhT) | outH: planar fp16 (Q/K) | outF: fp32
// 128x128 tile, BK=32, 512 threads
// ===========================================================================
#define PL_E 5120
#define PL_B (PL_E*2)
#define BUF1_B (2*PL_B)
#define GEMM1_SMEM (2*BUF1_B)

__global__ __launch_bounds__(512) void gemm_f16_1t(
    const __half* __restrict__ A, const __half* __restrict__ B,
    const float* __restrict__ bias, const float* __restrict__ npm, float scale,
    float* __restrict__ outF, __half* __restrict__ outH, __half* __restrict__ outT)
{
    extern __shared__ char sm[];
    const uint32_t smb = smem_u32(sm);
    const int tid = threadIdx.x, wid = tid >> 5, lane = tid & 31;
    const int g = lane >> 2, tg = lane & 3;
    const int bm = blockIdx.y * 128, bn = blockIdx.x * 128;
    const int wm = (wid & 1) * 64, wn = (wid >> 1) * 16;
    const int lrow = lane & 15, lkh = (lane >> 4) * 16;

    const __half* srcs[2] = { A + (size_t)bm * DD, B + (size_t)bn * DD };
    const int frow = tid >> 2, fc = tid & 3;

    float acc[4][2][4];
#pragma unroll
    for (int mi = 0; mi < 4; mi++)
#pragma unroll
        for (int ni = 0; ni < 2; ni++)
#pragma unroll
            for (int r = 0; r < 4; r++) acc[mi][ni][r] = 0.f;

#pragma unroll
    for (int i = 0; i < 2; i++)
        cp16(smb + i * PL_B + frow * 80 + fc * 16, srcs[i] + (size_t)frow * DD + fc * 8);
    CP_COMMIT;

    for (int kt = 0; kt < 32; kt++) {
        if (kt < 31) {
#pragma unroll
            for (int i = 0; i < 2; i++)
                cp16(smb + ((kt + 1) & 1) * BUF1_B + i * PL_B + frow * 80 + fc * 16,
                     srcs[i] + (size_t)frow * DD + (kt + 1) * 32 + fc * 8);
            CP_COMMIT;
            CP_WAIT1;
        } else {
            CP_WAIT0;
        }
        __syncthreads();

        const uint32_t bufb = smb + (kt & 1) * BUF1_B;
#pragma unroll
        for (int ks = 0; ks < 2; ks++) {
            uint32_t a_h[4][4], b4[4], b_h[2][2];
#pragma unroll
            for (int mi = 0; mi < 4; mi++)
                ldsm4(a_h[mi][0], a_h[mi][1], a_h[mi][2], a_h[mi][3],
                      bufb + (wm + mi * 16 + lrow) * 80 + ks * 32 + lkh);
            ldsm4(b4[0], b4[1], b4[2], b4[3],
                  bufb + PL_B + (wn + lrow) * 80 + ks * 32 + lkh);
            b_h[0][0] = b4[0]; b_h[0][1] = b4[2];
            b_h[1][0] = b4[1]; b_h[1][1] = b4[3];
#pragma unroll
            for (int mi = 0; mi < 4; mi++)
#pragma unroll
                for (int ni = 0; ni < 2; ni++)
                    mma_f16(acc[mi][ni], a_h[mi], b_h[ni]);
        }
        __syncthreads();
    }

    if (outT) {
        __half* smT = (__half*)sm;
#pragma unroll
        for (int mi = 0; mi < 4; mi++) {
            int r = wm + mi * 16 + g;
            float nv0 = npm[bm + r] * scale, nv1 = npm[bm + r + 8] * scale;
#pragma unroll
            for (int ni = 0; ni < 2; ni++) {
                int c = wn + ni * 8 + 2 * tg;
                float b0 = bias[bn + c], b1 = bias[bn + c + 1];
                smT[c * 136 + r]           = __float2half((acc[mi][ni][0] + b0) * nv0);
                smT[(c + 1) * 136 + r]     = __float2half((acc[mi][ni][1] + b1) * nv0);
                smT[c * 136 + r + 8]       = __float2half((acc[mi][ni][2] + b0) * nv1);
                smT[(c + 1) * 136 + r + 8] = __float2half((acc[mi][ni][3] + b1) * nv1);
            }
        }
        __syncthreads();
        const int b = bm >> 10, token0 = bm & 1023;
#pragma unroll
        for (int p = 0; p < 4; p++) {
            int cr = (tid >> 4) + p * 32;
            int unit = tid & 15;
            int C = bn + cr;
            int h = C >> 6, d = C & 63;
            size_t dst = ((size_t)(b * 16 + h) * 64 + d) * 1024 + token0 + unit * 8;
            *(uint4*)&outT[dst] = *(const uint4*)&smT[cr * 136 + unit * 8];
        }
    } else if (outH) {
#pragma unroll
        for (int mi = 0; mi < 4; mi++) {
            int r0 = bm + wm + mi * 16 + g, r1 = r0 + 8;
            float nv0 = npm[r0] * scale, nv1 = npm[r1] * scale;
#pragma unroll
            for (int ni = 0; ni < 2; ni++) {
                int c0 = bn + wn + ni * 8 + 2 * tg;
                float b0 = bias[c0], b1 = bias[c0 + 1];
                *(__half2*)&outH[(size_t)r0 * DD + c0] =
                    __floats2half2_rn((acc[mi][ni][0] + b0) * nv0, (acc[mi][ni][1] + b1) * nv0);
                *(__half2*)&outH[(size_t)r1 * DD + c0] =
                    __floats2half2_rn((acc[mi][ni][2] + b0) * nv1, (acc[mi][ni][3] + b1) * nv1);
            }
        }
    } else {
#pragma unroll
        for (int mi = 0; mi < 4; mi++) {
            int r0 = bm + wm + mi * 16 + g, r1 = r0 + 8;
            float nv0 = npm[r0] * scale, nv1 = npm[r1] * scale;
#pragma unroll
            for (int ni = 0; ni < 2; ni++) {
                int c0 = bn + wn + ni * 8 + 2 * tg;
                float b0 = bias[c0], b1 = bias[c0 + 1];
                *(float2*)&outF[(size_t)r0 * DD + c0] =
                    make_float2((acc[mi][ni][0] + b0) * nv0, (acc[mi][ni][1] + b1) * nv0);
                *(float2*)&outF[(size_t)r1 * DD + c0] =
                    make_float2((acc[mi][ni][2] + b0) * nv1, (acc[mi][ni][3] + b1) * nv1);
            }
        }
    }
}

// ===========================================================================
// Fused attention, 64-row q-tile: block = (b,h) x 64 q-rows, 512 threads
// 16 warps: 4 wq (16 rows each) x 4 wk (32 k-cols / 16 d-cols each)
// S-phase: QK^T -> byte-mask -> e=exp(s)/16 -> P fp16 (unnorm) + reg sums
// -> inv -> attn write -> PV (V^T double-buffered) -> ctx*inv
// smem: P 64x2096=134144 @0 | red 1024 @134144 | invs 256 @135168 |
//       Q 9216 @135424 | K 2x18432 @144640 | Mbyte 2x9216 @181504 = 199936
// PV overlay: VT 2x17408 @144640
// ===========================================================================
#define POFF 0
#define PSTRB 2096
#define REDOFF 134144
#define INVOFF 135168
#define QOFF 135424
#define KOFF 144640
#define KBUF 18432
#define MOFF 181504
#define MBUF 9216
#define MSTR 144
#define VTBUF 17408
#define VTSTRB 272
#define ATT_SMEM 199936

__global__ __launch_bounds__(512) void attn_kernel(
    const __half* __restrict__ qh, const __half* __restrict__ kh,
    const __half* __restrict__ vhT, const uint8_t* __restrict__ maskb,
    float* __restrict__ attn, __half* __restrict__ ctx)
{
    extern __shared__ char sm[];
    const uint32_t smb = smem_u32(sm);
    float* red = (float*)(sm + REDOFF);       // [64][4]
    float* invs = (float*)(sm + INVOFF);      // [64]

    const int tid = threadIdx.x, wid = tid >> 5, lane = tid & 31;
    const int g = lane >> 2, tg = lane & 3;
    const int lrow = lane & 15, lkh = (lane >> 4) * 16;
    const int bh = blockIdx.x;
    const int b = bh >> 4, h = bh & 15;
    const int q0 = blockIdx.y * 64;
    const int wq = wid & 3;
    const int wk = wid >> 2;
    const int row0 = wq * 16 + g;

    const __half* qp_g = qh + ((size_t)b * LL + q0) * DD + h * DK;
    const __half* kp_g = kh + (size_t)b * LL * DD + h * DK;
    const uint8_t* mp_g = maskb + ((size_t)b * LL + q0) * LL;
    const __half* vTp = vhT + (size_t)bh * DK * LL;
    float* attnBase = attn + ((size_t)bh * LL + q0) * LL;

    // Q load (64x64) + {K0,M0} chunk 0
    {
        int row = tid >> 3, c8 = tid & 7;
        cp16(smb + QOFF + row * 144 + c8 * 16, qp_g + (size_t)row * DD + c8 * 8);
    }
#pragma unroll
    for (int j = 0; j < 2; j++) {
        int idx = tid + 512 * j;               // 0..1023
        int row = idx >> 3, c8 = idx & 7;
        cp16(smb + KOFF + row * 144 + c8 * 16, kp_g + (size_t)row * DD + c8 * 8);
    }
    {
        int mr = tid >> 3, mc = tid & 7;       // 64 rows x 8 groups of 16B
        cp16(smb + MOFF + mr * MSTR + mc * 16, mp_g + (size_t)mr * LL + mc * 16);
    }
    CP_COMMIT;

    // ---- S-phase with fused exp over 8 chunks (K,M double-buffered) ----
    float psum0 = 0.f, psum1 = 0.f;
    for (int kc = 0; kc < 8; kc++) {
        if (kc < 7) {
#pragma unroll
            for (int j = 0; j < 2; j++) {
                int idx = tid + 512 * j;
                int row = idx >> 3, c8 = idx & 7;
                cp16(smb + KOFF + ((kc + 1) & 1) * KBUF + row * 144 + c8 * 16,
                     kp_g + (size_t)((kc + 1) * 128 + row) * DD + c8 * 8);
            }
            {
                int mr = tid >> 3, mc = tid & 7;
                cp16(smb + MOFF + ((kc + 1) & 1) * MBUF + mr * MSTR + mc * 16,
                     mp_g + (size_t)mr * LL + (kc + 1) * 128 + mc * 16);
            }
            CP_COMMIT;
            CP_WAIT1;
        } else {
            CP_WAIT0;
        }
        __syncthreads();

        const uint32_t kb = smb + KOFF + (kc & 1) * KBUF;
        const uint8_t* mb = (const uint8_t*)(sm + MOFF + (kc & 1) * MBUF);
        float sacc[4][4];
#pragma unroll
        for (int ni = 0; ni < 4; ni++)
#pragma unroll
            for (int r = 0; r < 4; r++) sacc[ni][r] = 0.f;

#pragma unroll
        for (int ks = 0; ks < 4; ks++) {
            uint32_t a_h[4], b4a[4], b4b[4], b_h[4][2];
            ldsm4(a_h[0], a_h[1], a_h[2], a_h[3],
                  smb + QOFF + (wq * 16 + lrow) * 144 + ks * 32 + lkh);
            ldsm4(b4a[0], b4a[1], b4a[2], b4a[3],
                  kb + (wk * 32 + lrow) * 144 + ks * 32 + lkh);
            ldsm4(b4b[0], b4b[1], b4b[2], b4b[3],
                  kb + (wk * 32 + 16 + lrow) * 144 + ks * 32 + lkh);
            b_h[0][0] = b4a[0]; b_h[0][1] = b4a[2];
            b_h[1][0] = b4a[1]; b_h[1][1] = b4a[3];
            b_h[2][0] = b4b[0]; b_h[2][1] = b4b[2];
            b_h[3][0] = b4b[1]; b_h[3][1] = b4b[3];
#pragma unroll
            for (int ni = 0; ni < 4; ni++)
                mma_f16(sacc[ni], a_h, b_h[ni]);
        }
        // mask + exp + store unnormalized P fp16 + accumulate sums
#pragma unroll
        for (int ni = 0; ni < 4; ni++) {
            int cl = wk * 32 + ni * 8 + 2 * tg;        // local col 0..127
            uint8_t m00 = mb[row0 * MSTR + cl], m01 = mb[row0 * MSTR + cl + 1];
            uint8_t m10 = mb[(row0 + 8) * MSTR + cl], m11 = mb[(row0 + 8) * MSTR + cl + 1];
            float e0 = m00 ? 0.f : __expf(sacc[ni][0]) * 0.0625f;
            float e1 = m01 ? 0.f : __expf(sacc[ni][1]) * 0.0625f;
            float e2 = m10 ? 0.f : __expf(sacc[ni][2]) * 0.0625f;
            float e3 = m11 ? 0.f : __expf(sacc[ni][3]) * 0.0625f;
            psum0 += e0 + e1;
            psum1 += e2 + e3;
            int c = kc * 128 + cl;
            *(__half2*)(sm + POFF + row0 * PSTRB + c * 2)       = __floats2half2_rn(e0, e1);
            *(__half2*)(sm + POFF + (row0 + 8) * PSTRB + c * 2) = __floats2half2_rn(e2, e3);
        }
    }

    // ---- reduce row sums: tg shuffle then across 4 wk warps ----
    psum0 += __shfl_xor_sync(0xffffffffu, psum0, 1);
    psum0 += __shfl_xor_sync(0xffffffffu, psum0, 2);
    psum1 += __shfl_xor_sync(0xffffffffu, psum1, 1);
    psum1 += __shfl_xor_sync(0xffffffffu, psum1, 2);
    if (tg == 0) {
        red[row0 * 4 + wk] = psum0;
        red[(row0 + 8) * 4 + wk] = psum1;
    }
    __syncthreads();
    if (wk == 0 && tg == 0) {
        float s0 = red[row0 * 4] + red[row0 * 4 + 1] + red[row0 * 4 + 2] + red[row0 * 4 + 3];
        float s1 = red[(row0 + 8) * 4] + red[(row0 + 8) * 4 + 1] +
                   red[(row0 + 8) * 4 + 2] + red[(row0 + 8) * 4 + 3];
        invs[row0] = 1.f / s0;
        invs[row0 + 8] = 1.f / s1;
    }
    __syncthreads();   // P + invs complete; K/mask regions dead -> VT

    // prefetch V^T chunk 0 into K region
#pragma unroll
    for (int j = 0; j < 2; j++) {
        int idx = tid + 512 * j;
        int d = idx >> 4, tk = idx & 15;
        cp16(smb + KOFF + d * VTSTRB + tk * 16, vTp + (size_t)d * LL + tk * 8);
    }
    CP_COMMIT;

    // ---- attn write: read P, scale by inv, coalesced fp32 store ----
#pragma unroll
    for (int rr = 0; rr < 4; rr++) {
        int r = wid * 4 + rr;
        float inv = invs[r];
        const __half2* Pr = (const __half2*)(sm + POFF + r * PSTRB);
        float* dst = attnBase + (size_t)r * LL;
#pragma unroll 4
        for (int c2 = lane; c2 < 512; c2 += 32) {
            float2 p2 = __half22float2(Pr[c2]);
            *(float2*)&dst[c2 * 2] = make_float2(p2.x * inv, p2.y * inv);
        }
    }

    // ---- PV on unnormalized P; warp tile 16q x 16d; V^T double-buffered ----
    float pacc[2][4];
#pragma unroll
    for (int ni = 0; ni < 2; ni++)
#pragma unroll
        for (int r = 0; r < 4; r++) pacc[ni][r] = 0.f;

    for (int vc = 0; vc < 8; vc++) {
        if (vc < 7) {
#pragma unroll
            for (int j = 0; j < 2; j++) {
                int idx = tid + 512 * j;
                int d = idx >> 4, tk = idx & 15;
                cp16(smb + KOFF + ((vc + 1) & 1) * VTBUF + d * VTSTRB + tk * 16,
                     vTp + (size_t)d * LL + (vc + 1) * 128 + tk * 8);
            }
            CP_COMMIT;
            CP_WAIT1;
        } else {
            CP_WAIT0;
        }
        __syncthreads();

        const uint32_t vtb = smb + KOFF + (vc & 1) * VTBUF;
        const uint32_t pb = smb + POFF + (wq * 16) * PSTRB + vc * 256;
#pragma unroll
        for (int kk = 0; kk < 8; kk++) {
            uint32_t a[4], b4[4], bfr[2][2];
            ldsm4(a[0], a[1], a[2], a[3], pb + lrow * PSTRB + kk * 32 + lkh);
            ldsm4(b4[0], b4[1], b4[2], b4[3],
                  vtb + (wk * 16 + lrow) * VTSTRB + kk * 32 + lkh);
            bfr[0][0] = b4[0]; bfr[0][1] = b4[2];
            bfr[1][0] = b4[1]; bfr[1][1] = b4[3];
            mma_f16(pacc[0], a, bfr[0]);
            mma_f16(pacc[1], a, bfr[1]);
        }
        __syncthreads();
    }

    {
        float inv0 = invs[row0], inv1 = invs[row0 + 8];
        size_t r0 = (size_t)b * LL + q0 + row0;
#pragma unroll
        for (int ni = 0; ni < 2; ni++) {
            int c = h * DK + wk * 16 + ni * 8 + 2 * tg;
            *(__half2*)&ctx[r0 * DD + c] =
                __floats2half2_rn(pacc[ni][0] * inv0, pacc[ni][1] * inv0);
            *(__half2*)&ctx[(r0 + 8) * DD + c] =
                __floats2half2_rn(pacc[ni][2] * inv1, pacc[ni][3] * inv1);
        }
    }
}

// ---------------------------------------------------------------------------
// LayerNorm(proj + residual) * g + b
// ---------------------------------------------------------------------------
__global__ __launch_bounds__(256) void ln_kernel(
    const float* __restrict__ proj, const float* __restrict__ resid,
    const float* __restrict__ gam, const float* __restrict__ bet,
    float* __restrict__ out)
{
    __shared__ float red[8];
    const int row = blockIdx.x;
    const int tid = threadIdx.x;
    const int c0 = tid * 4;
    const int lane = tid & 31, wid = tid >> 5;

    float4 pv = *(const float4*)(proj + (size_t)row * DD + c0);
    float4 rv = *(const float4*)(resid + (size_t)row * DD + c0);
    float x0 = pv.x + rv.x, x1 = pv.y + rv.y, x2 = pv.z + rv.z, x3 = pv.w + rv.w;

    float s = x0 + x1 + x2 + x3;
#pragma unroll
    for (int o = 16; o; o >>= 1) s += __shfl_xor_sync(0xffffffffu, s, o);
    if (lane == 0) red[wid] = s;
    __syncthreads();
    float tot = (lane < 8) ? red[lane] : 0.f;
#pragma unroll
    for (int o = 4; o; o >>= 1) tot += __shfl_xor_sync(0xffffffffu, tot, o);
    tot = __shfl_sync(0xffffffffu, tot, 0);
    float mean = tot * (1.f / 1024.f);

    float d0 = x0 - mean, d1 = x1 - mean, d2 = x2 - mean, d3 = x3 - mean;
    float sq = d0 * d0 + d1 * d1 + d2 * d2 + d3 * d3;
#pragma unroll
    for (int o = 16; o; o >>= 1) sq += __shfl_xor_sync(0xffffffffu, sq, o);
    __syncthreads();
    if (lane == 0) red[wid] = sq;
    __syncthreads();
    float tot2 = (lane < 8) ? red[lane] : 0.f;
#pragma unroll
    for (int o = 4; o; o >>= 1) tot2 += __shfl_xor_sync(0xffffffffu, tot2, o);
    tot2 = __shfl_sync(0xffffffffu, tot2, 0);
    float k = rsqrtf(tot2 * (1.f / 1024.f) + 1e-5f);

    float4 gv = *(const float4*)(gam + c0);
    float4 bv = *(const float4*)(bet + c0);
    float4 ov;
    ov.x = d0 * k * gv.x + bv.x;
    ov.y = d1 * k * gv.y + bv.y;
    ov.z = d2 * k * gv.z + bv.z;
    ov.w = d3 * k * gv.w + bv.w;
    *(float4*)&out[(size_t)row * DD + c0] = ov;
}

// ---------------------------------------------------------------------------
extern "C" void kernel_launch(void* const* d_in, const int* in_sizes, int n_in,
                              void* d_out, int out_size)
{
    const float* q    = (const float*)d_in[0];
    const float* k    = (const float*)d_in[1];
    const float* v    = (const float*)d_in[2];
    const int*   mask = (const int*)  d_in[3];
    const float* npm  = (const float*)d_in[4];
    const float* Wq   = (const float*)d_in[5];
    const float* bq   = (const float*)d_in[6];
    const float* Wk   = (const float*)d_in[7];
    const float* bk   = (const float*)d_in[8];
    const float* Wv   = (const float*)d_in[9];
    const float* bv   = (const float*)d_in[10];
    const float* Wf   = (const float*)d_in[11];
    const float* bf   = (const float*)d_in[12];
    const float* ln_g = (const float*)d_in[13];
    const float* ln_b = (const float*)d_in[14];

    float* out  = (float*)d_out;
    float* attn = out + (size_t)BB * LL * DD;

    __half *qh, *kh, *vhT, *ctx, *as, *ws;
    float *proj;
    uint8_t* mb;
    cudaGetSymbolAddress((void**)&qh,  g_qh);
    cudaGetSymbolAddress((void**)&kh,  g_kh);
    cudaGetSymbolAddress((void**)&vhT, g_vhT);
    cudaGetSymbolAddress((void**)&ctx, g_ctx);
    cudaGetSymbolAddress((void**)&proj, g_proj);
    cudaGetSymbolAddress((void**)&as,  g_as);
    cudaGetSymbolAddress((void**)&ws,  g_ws);
    cudaGetSymbolAddress((void**)&mb,  g_mb);

    cudaFuncSetAttribute(gemm_f16_1t, cudaFuncAttributeMaxDynamicSharedMemorySize, GEMM1_SMEM);
    cudaFuncSetAttribute(attn_kernel, cudaFuncAttributeMaxDynamicSharedMemorySize, ATT_SMEM);

    const int nA4 = ROWS_TOT * DD / 4;
    const int nW4 = DD * DD / 4;
    const int nM4 = BB * LL * LL / 4;    // 2,097,152
    dim3 gG(DD / 128, ROWS_TOT / 128);   // (8, 64)

    // mask -> byte (overlaps with projection pipeline)
    mask_byte<<<(nM4 + 255) / 256, 256>>>(mask, mb, nM4);

    // Q projection (scale 1/8 folded) -> fp16
    conv_f16<<<(nA4 + 255) / 256, 256>>>(q, as, nA4);
    conv_f16<<<(nW4 + 255) / 256, 256>>>(Wq, ws, nW4);
    gemm_f16_1t<<<gG, 512, GEMM1_SMEM>>>(as, ws, bq, npm, 0.125f, nullptr, qh, nullptr);
    // K projection -> fp16
    conv_f16<<<(nA4 + 255) / 256, 256>>>(k, as, nA4);
    conv_f16<<<(nW4 + 255) / 256, 256>>>(Wk, ws, nW4);
    gemm_f16_1t<<<gG, 512, GEMM1_SMEM>>>(as, ws, bk, npm, 1.0f, nullptr, kh, nullptr);
    // V projection -> transposed fp16 vhT
    conv_f16<<<(nA4 + 255) / 256, 256>>>(v, as, nA4);
    conv_f16<<<(nW4 + 255) / 256, 256>>>(Wv, ws, nW4);
    gemm_f16_1t<<<gG, 512, GEMM1_SMEM>>>(as, ws, bv, npm, 1.0f, nullptr, nullptr, vhT);

    // Fused attention, 64-row q-tiles (ctx out as fp16)
    attn_kernel<<<dim3(BB * HH, LL / 64), 512, ATT_SMEM>>>(
        qh, kh, vhT, mb, attn, ctx);

    // Output projection (ctx fp16 direct) -> fp32, then LN
    conv_f16<<<(nW4 + 255) / 256, 256>>>(Wf, ws, nW4);
    gemm_f16_1t<<<gG, 512, GEMM1_SMEM>>>(ctx, ws, bf, npm, 1.0f, proj, nullptr, nullptr);

    ln_kernel<<<ROWS_TOT, 256>>>(proj, q, ln_g, ln_b, out);
}

// round 17
// speedup vs baseline: 1.9577x; 1.0351x over previous
#include <cuda_runtime.h>
#include <cuda_fp16.h>
#include <math.h>
#include <cstdint>

#define BB 8
#define LL 1024
#define DD 1024
#define HH 16
#define DK 64
#define ROWS_TOT (BB*LL)          // 8192

// Scratch (device globals)
__device__ __half g_qh [(size_t)ROWS_TOT * DD];   // fp16 q heads (scaled 1/8)
__device__ __half g_kh [(size_t)ROWS_TOT * DD];   // fp16 k heads
__device__ __half g_vhT[(size_t)ROWS_TOT * DD];   // [b][h][d][token] fp16
__device__ __half g_ctx[(size_t)ROWS_TOT * DD];   // fp16
__device__ float  g_proj[(size_t)ROWS_TOT * DD];
__device__ __half g_as [(size_t)ROWS_TOT * DD];
__device__ __half g_ws [(size_t)DD * DD];
__device__ uint8_t g_mb[(size_t)BB * LL * LL];    // byte mask

// ---------------------------------------------------------------------------
// helpers
// ---------------------------------------------------------------------------
__device__ __forceinline__ uint32_t smem_u32(const void* p) {
    uint32_t a;
    asm("{ .reg .u64 t; cvta.to.shared.u64 t, %1; cvt.u32.u64 %0, t; }" : "=r"(a) : "l"(p));
    return a;
}
__device__ __forceinline__ void cp16(uint32_t dst, const void* src) {
    asm volatile("cp.async.cg.shared.global [%0], [%1], 16;" :: "r"(dst), "l"(src));
}
#define CP_COMMIT asm volatile("cp.async.commit_group;" ::: "memory")
#define CP_WAIT1  asm volatile("cp.async.wait_group 1;" ::: "memory")
#define CP_WAIT0  asm volatile("cp.async.wait_group 0;" ::: "memory")

__device__ __forceinline__ void mma_f16(float* c, const uint32_t* a, const uint32_t* b) {
    asm volatile(
        "mma.sync.aligned.m16n8k16.row.col.f32.f16.f16.f32 "
        "{%0,%1,%2,%3},{%4,%5,%6,%7},{%8,%9},{%0,%1,%2,%3};"
        : "+f"(c[0]), "+f"(c[1]), "+f"(c[2]), "+f"(c[3])
        : "r"(a[0]), "r"(a[1]), "r"(a[2]), "r"(a[3]), "r"(b[0]), "r"(b[1]));
}
__device__ __forceinline__ void ldsm4(uint32_t& r0, uint32_t& r1, uint32_t& r2,
                                      uint32_t& r3, uint32_t addr) {
    asm volatile("ldmatrix.sync.aligned.m8n8.x4.shared.b16 {%0,%1,%2,%3}, [%4];"
                 : "=r"(r0), "=r"(r1), "=r"(r2), "=r"(r3) : "r"(addr));
}

// f32 -> fp16 convert
__global__ __launch_bounds__(256) void conv_f16(
    const float* __restrict__ x, __half* __restrict__ hi, int n4)
{
    int i = blockIdx.x * blockDim.x + threadIdx.x;
    if (i >= n4) return;
    float4 v = ((const float4*)x)[i];
    ((__half2*)hi)[i * 2]     = __floats2half2_rn(v.x, v.y);
    ((__half2*)hi)[i * 2 + 1] = __floats2half2_rn(v.z, v.w);
}

// int32 mask -> uint8 mask
__global__ __launch_bounds__(256) void mask_byte(
    const int* __restrict__ m, uint8_t* __restrict__ mb, int n4)
{
    int i = blockIdx.x * blockDim.x + threadIdx.x;
    if (i >= n4) return;
    int4 v = ((const int4*)m)[i];
    uchar4 o;
    o.x = v.x ? 1 : 0; o.y = v.y ? 1 : 0;
    o.z = v.z ? 1 : 0; o.w = v.w ? 1 : 0;
    ((uchar4*)mb)[i] = o;
}

// ===========================================================================
// single-term fp16 GEMM. Warp tile 32x32 (16 warps: 4m x 4n), block 128x128,
// BK=32, 512 threads. Output modes: outT transposed | outH fp16 | outF fp32
// ===========================================================================
#define PL_E 5120
#define PL_B (PL_E*2)
#define BUF1_B (2*PL_B)
#define GEMM1_SMEM (2*BUF1_B)

__global__ __launch_bounds__(512) void gemm_f16_1t(
    const __half* __restrict__ A, const __half* __restrict__ B,
    const float* __restrict__ bias, const float* __restrict__ npm, float scale,
    float* __restrict__ outF, __half* __restrict__ outH, __half* __restrict__ outT)
{
    extern __shared__ char sm[];
    const uint32_t smb = smem_u32(sm);
    const int tid = threadIdx.x, wid = tid >> 5, lane = tid & 31;
    const int g = lane >> 2, tg = lane & 3;
    const int bm = blockIdx.y * 128, bn = blockIdx.x * 128;
    const int wm = (wid & 3) * 32, wn = (wid >> 2) * 32;
    const int lrow = lane & 15, lkh = (lane >> 4) * 16;

    const __half* srcs[2] = { A + (size_t)bm * DD, B + (size_t)bn * DD };
    const int frow = tid >> 2, fc = tid & 3;

    float acc[2][4][4];
#pragma unroll
    for (int mi = 0; mi < 2; mi++)
#pragma unroll
        for (int ni = 0; ni < 4; ni++)
#pragma unroll
            for (int r = 0; r < 4; r++) acc[mi][ni][r] = 0.f;

#pragma unroll
    for (int i = 0; i < 2; i++)
        cp16(smb + i * PL_B + frow * 80 + fc * 16, srcs[i] + (size_t)frow * DD + fc * 8);
    CP_COMMIT;

    for (int kt = 0; kt < 32; kt++) {
        if (kt < 31) {
#pragma unroll
            for (int i = 0; i < 2; i++)
                cp16(smb + ((kt + 1) & 1) * BUF1_B + i * PL_B + frow * 80 + fc * 16,
                     srcs[i] + (size_t)frow * DD + (kt + 1) * 32 + fc * 8);
            CP_COMMIT;
            CP_WAIT1;
        } else {
            CP_WAIT0;
        }
        __syncthreads();

        const uint32_t bufb = smb + (kt & 1) * BUF1_B;
#pragma unroll
        for (int ks = 0; ks < 2; ks++) {
            uint32_t a_h[2][4], b4a[4], b4b[4], b_h[4][2];
#pragma unroll
            for (int mi = 0; mi < 2; mi++)
                ldsm4(a_h[mi][0], a_h[mi][1], a_h[mi][2], a_h[mi][3],
                      bufb + (wm + mi * 16 + lrow) * 80 + ks * 32 + lkh);
            ldsm4(b4a[0], b4a[1], b4a[2], b4a[3],
                  bufb + PL_B + (wn + lrow) * 80 + ks * 32 + lkh);
            ldsm4(b4b[0], b4b[1], b4b[2], b4b[3],
                  bufb + PL_B + (wn + 16 + lrow) * 80 + ks * 32 + lkh);
            b_h[0][0] = b4a[0]; b_h[0][1] = b4a[2];
            b_h[1][0] = b4a[1]; b_h[1][1] = b4a[3];
            b_h[2][0] = b4b[0]; b_h[2][1] = b4b[2];
            b_h[3][0] = b4b[1]; b_h[3][1] = b4b[3];
#pragma unroll
            for (int mi = 0; mi < 2; mi++)
#pragma unroll
                for (int ni = 0; ni < 4; ni++)
                    mma_f16(acc[mi][ni], a_h[mi], b_h[ni]);
        }
        __syncthreads();
    }

    if (outT) {
        __half* smT = (__half*)sm;
#pragma unroll
        for (int mi = 0; mi < 2; mi++) {
            int r = wm + mi * 16 + g;
            float nv0 = npm[bm + r] * scale, nv1 = npm[bm + r + 8] * scale;
#pragma unroll
            for (int ni = 0; ni < 4; ni++) {
                int c = wn + ni * 8 + 2 * tg;
                float b0 = bias[bn + c], b1 = bias[bn + c + 1];
                smT[c * 136 + r]           = __float2half((acc[mi][ni][0] + b0) * nv0);
                smT[(c + 1) * 136 + r]     = __float2half((acc[mi][ni][1] + b1) * nv0);
                smT[c * 136 + r + 8]       = __float2half((acc[mi][ni][2] + b0) * nv1);
                smT[(c + 1) * 136 + r + 8] = __float2half((acc[mi][ni][3] + b1) * nv1);
            }
        }
        __syncthreads();
        const int b = bm >> 10, token0 = bm & 1023;
#pragma unroll
        for (int p = 0; p < 4; p++) {
            int cr = (tid >> 4) + p * 32;
            int unit = tid & 15;
            int C = bn + cr;
            int h = C >> 6, d = C & 63;
            size_t dst = ((size_t)(b * 16 + h) * 64 + d) * 1024 + token0 + unit * 8;
            *(uint4*)&outT[dst] = *(const uint4*)&smT[cr * 136 + unit * 8];
        }
    } else if (outH) {
#pragma unroll
        for (int mi = 0; mi < 2; mi++) {
            int r0 = bm + wm + mi * 16 + g, r1 = r0 + 8;
            float nv0 = npm[r0] * scale, nv1 = npm[r1] * scale;
#pragma unroll
            for (int ni = 0; ni < 4; ni++) {
                int c0 = bn + wn + ni * 8 + 2 * tg;
                float b0 = bias[c0], b1 = bias[c0 + 1];
                *(__half2*)&outH[(size_t)r0 * DD + c0] =
                    __floats2half2_rn((acc[mi][ni][0] + b0) * nv0, (acc[mi][ni][1] + b1) * nv0);
                *(__half2*)&outH[(size_t)r1 * DD + c0] =
                    __floats2half2_rn((acc[mi][ni][2] + b0) * nv1, (acc[mi][ni][3] + b1) * nv1);
            }
        }
    } else {
#pragma unroll
        for (int mi = 0; mi < 2; mi++) {
            int r0 = bm + wm + mi * 16 + g, r1 = r0 + 8;
            float nv0 = npm[r0] * scale, nv1 = npm[r1] * scale;
#pragma unroll
            for (int ni = 0; ni < 4; ni++) {
                int c0 = bn + wn + ni * 8 + 2 * tg;
                float b0 = bias[c0], b1 = bias[c0 + 1];
                *(float2*)&outF[(size_t)r0 * DD + c0] =
                    make_float2((acc[mi][ni][0] + b0) * nv0, (acc[mi][ni][1] + b1) * nv0);
                *(float2*)&outF[(size_t)r1 * DD + c0] =
                    make_float2((acc[mi][ni][2] + b0) * nv1, (acc[mi][ni][3] + b1) * nv1);
            }
        }
    }
}

// ===========================================================================
// Fused attention, 64-row q-tile (R16, proven): block = (b,h) x 64 q-rows,
// 512 threads, 16 warps: 4 wq x 4 wk
// ===========================================================================
#define POFF 0
#define PSTRB 2096
#define REDOFF 134144
#define INVOFF 135168
#define QOFF 135424
#define KOFF 144640
#define KBUF 18432
#define MOFF 181504
#define MBUF 9216
#define MSTR 144
#define VTBUF 17408
#define VTSTRB 272
#define ATT_SMEM 199936

__global__ __launch_bounds__(512) void attn_kernel(
    const __half* __restrict__ qh, const __half* __restrict__ kh,
    const __half* __restrict__ vhT, const uint8_t* __restrict__ maskb,
    float* __restrict__ attn, __half* __restrict__ ctx)
{
    extern __shared__ char sm[];
    const uint32_t smb = smem_u32(sm);
    float* red = (float*)(sm + REDOFF);       // [64][4]
    float* invs = (float*)(sm + INVOFF);      // [64]

    const int tid = threadIdx.x, wid = tid >> 5, lane = tid & 31;
    const int g = lane >> 2, tg = lane & 3;
    const int lrow = lane & 15, lkh = (lane >> 4) * 16;
    const int bh = blockIdx.x;
    const int b = bh >> 4, h = bh & 15;
    const int q0 = blockIdx.y * 64;
    const int wq = wid & 3;
    const int wk = wid >> 2;
    const int row0 = wq * 16 + g;

    const __half* qp_g = qh + ((size_t)b * LL + q0) * DD + h * DK;
    const __half* kp_g = kh + (size_t)b * LL * DD + h * DK;
    const uint8_t* mp_g = maskb + ((size_t)b * LL + q0) * LL;
    const __half* vTp = vhT + (size_t)bh * DK * LL;
    float* attnBase = attn + ((size_t)bh * LL + q0) * LL;

    // Q load (64x64) + {K0,M0} chunk 0
    {
        int row = tid >> 3, c8 = tid & 7;
        cp16(smb + QOFF + row * 144 + c8 * 16, qp_g + (size_t)row * DD + c8 * 8);
    }
#pragma unroll
    for (int j = 0; j < 2; j++) {
        int idx = tid + 512 * j;
        int row = idx >> 3, c8 = idx & 7;
        cp16(smb + KOFF + row * 144 + c8 * 16, kp_g + (size_t)row * DD + c8 * 8);
    }
    {
        int mr = tid >> 3, mc = tid & 7;
        cp16(smb + MOFF + mr * MSTR + mc * 16, mp_g + (size_t)mr * LL + mc * 16);
    }
    CP_COMMIT;

    // ---- S-phase with fused exp over 8 chunks (K,M double-buffered) ----
    float psum0 = 0.f, psum1 = 0.f;
    for (int kc = 0; kc < 8; kc++) {
        if (kc < 7) {
#pragma unroll
            for (int j = 0; j < 2; j++) {
                int idx = tid + 512 * j;
                int row = idx >> 3, c8 = idx & 7;
                cp16(smb + KOFF + ((kc + 1) & 1) * KBUF + row * 144 + c8 * 16,
                     kp_g + (size_t)((kc + 1) * 128 + row) * DD + c8 * 8);
            }
            {
                int mr = tid >> 3, mc = tid & 7;
                cp16(smb + MOFF + ((kc + 1) & 1) * MBUF + mr * MSTR + mc * 16,
                     mp_g + (size_t)mr * LL + (kc + 1) * 128 + mc * 16);
            }
            CP_COMMIT;
            CP_WAIT1;
        } else {
            CP_WAIT0;
        }
        __syncthreads();

        const uint32_t kb = smb + KOFF + (kc & 1) * KBUF;
        const uint8_t* mb = (const uint8_t*)(sm + MOFF + (kc & 1) * MBUF);
        float sacc[4][4];
#pragma unroll
        for (int ni = 0; ni < 4; ni++)
#pragma unroll
            for (int r = 0; r < 4; r++) sacc[ni][r] = 0.f;

#pragma unroll
        for (int ks = 0; ks < 4; ks++) {
            uint32_t a_h[4], b4a[4], b4b[4], b_h[4][2];
            ldsm4(a_h[0], a_h[1], a_h[2], a_h[3],
                  smb + QOFF + (wq * 16 + lrow) * 144 + ks * 32 + lkh);
            ldsm4(b4a[0], b4a[1], b4a[2], b4a[3],
                  kb + (wk * 32 + lrow) * 144 + ks * 32 + lkh);
            ldsm4(b4b[0], b4b[1], b4b[2], b4b[3],
                  kb + (wk * 32 + 16 + lrow) * 144 + ks * 32 + lkh);
            b_h[0][0] = b4a[0]; b_h[0][1] = b4a[2];
            b_h[1][0] = b4a[1]; b_h[1][1] = b4a[3];
            b_h[2][0] = b4b[0]; b_h[2][1] = b4b[2];
            b_h[3][0] = b4b[1]; b_h[3][1] = b4b[3];
#pragma unroll
            for (int ni = 0; ni < 4; ni++)
                mma_f16(sacc[ni], a_h, b_h[ni]);
        }
        // mask + exp + store unnormalized P fp16 + accumulate sums
#pragma unroll
        for (int ni = 0; ni < 4; ni++) {
            int cl = wk * 32 + ni * 8 + 2 * tg;
            uint8_t m00 = mb[row0 * MSTR + cl], m01 = mb[row0 * MSTR + cl + 1];
            uint8_t m10 = mb[(row0 + 8) * MSTR + cl], m11 = mb[(row0 + 8) * MSTR + cl + 1];
            float e0 = m00 ? 0.f : __expf(sacc[ni][0]) * 0.0625f;
            float e1 = m01 ? 0.f : __expf(sacc[ni][1]) * 0.0625f;
            float e2 = m10 ? 0.f : __expf(sacc[ni][2]) * 0.0625f;
            float e3 = m11 ? 0.f : __expf(sacc[ni][3]) * 0.0625f;
            psum0 += e0 + e1;
            psum1 += e2 + e3;
            int c = kc * 128 + cl;
            *(__half2*)(sm + POFF + row0 * PSTRB + c * 2)       = __floats2half2_rn(e0, e1);
            *(__half2*)(sm + POFF + (row0 + 8) * PSTRB + c * 2) = __floats2half2_rn(e2, e3);
        }
    }

    // ---- reduce row sums ----
    psum0 += __shfl_xor_sync(0xffffffffu, psum0, 1);
    psum0 += __shfl_xor_sync(0xffffffffu, psum0, 2);
    psum1 += __shfl_xor_sync(0xffffffffu, psum1, 1);
    psum1 += __shfl_xor_sync(0xffffffffu, psum1, 2);
    if (tg == 0) {
        red[row0 * 4 + wk] = psum0;
        red[(row0 + 8) * 4 + wk] = psum1;
    }
    __syncthreads();
    if (wk == 0 && tg == 0) {
        float s0 = red[row0 * 4] + red[row0 * 4 + 1] + red[row0 * 4 + 2] + red[row0 * 4 + 3];
        float s1 = red[(row0 + 8) * 4] + red[(row0 + 8) * 4 + 1] +
                   red[(row0 + 8) * 4 + 2] + red[(row0 + 8) * 4 + 3];
        invs[row0] = 1.f / s0;
        invs[row0 + 8] = 1.f / s1;
    }
    __syncthreads();

    // prefetch V^T chunk 0 into K region
#pragma unroll
    for (int j = 0; j < 2; j++) {
        int idx = tid + 512 * j;
        int d = idx >> 4, tk = idx & 15;
        cp16(smb + KOFF + d * VTSTRB + tk * 16, vTp + (size_t)d * LL + tk * 8);
    }
    CP_COMMIT;

    // ---- attn write ----
#pragma unroll
    for (int rr = 0; rr < 4; rr++) {
        int r = wid * 4 + rr;
        float inv = invs[r];
        const __half2* Pr = (const __half2*)(sm + POFF + r * PSTRB);
        float* dst = attnBase + (size_t)r * LL;
#pragma unroll 4
        for (int c2 = lane; c2 < 512; c2 += 32) {
            float2 p2 = __half22float2(Pr[c2]);
            *(float2*)&dst[c2 * 2] = make_float2(p2.x * inv, p2.y * inv);
        }
    }

    // ---- PV on unnormalized P; warp tile 16q x 16d; V^T double-buffered ----
    float pacc[2][4];
#pragma unroll
    for (int ni = 0; ni < 2; ni++)
#pragma unroll
        for (int r = 0; r < 4; r++) pacc[ni][r] = 0.f;

    for (int vc = 0; vc < 8; vc++) {
        if (vc < 7) {
#pragma unroll
            for (int j = 0; j < 2; j++) {
                int idx = tid + 512 * j;
                int d = idx >> 4, tk = idx & 15;
                cp16(smb + KOFF + ((vc + 1) & 1) * VTBUF + d * VTSTRB + tk * 16,
                     vTp + (size_t)d * LL + (vc + 1) * 128 + tk * 8);
            }
            CP_COMMIT;
            CP_WAIT1;
        } else {
            CP_WAIT0;
        }
        __syncthreads();

        const uint32_t vtb = smb + KOFF + (vc & 1) * VTBUF;
        const uint32_t pb = smb + POFF + (wq * 16) * PSTRB + vc * 256;
#pragma unroll
        for (int kk = 0; kk < 8; kk++) {
            uint32_t a[4], b4[4], bfr[2][2];
            ldsm4(a[0], a[1], a[2], a[3], pb + lrow * PSTRB + kk * 32 + lkh);
            ldsm4(b4[0], b4[1], b4[2], b4[3],
                  vtb + (wk * 16 + lrow) * VTSTRB + kk * 32 + lkh);
            bfr[0][0] = b4[0]; bfr[0][1] = b4[2];
            bfr[1][0] = b4[1]; bfr[1][1] = b4[3];
            mma_f16(pacc[0], a, bfr[0]);
            mma_f16(pacc[1], a, bfr[1]);
        }
        __syncthreads();
    }

    {
        float inv0 = invs[row0], inv1 = invs[row0 + 8];
        size_t r0 = (size_t)b * LL + q0 + row0;
#pragma unroll
        for (int ni = 0; ni < 2; ni++) {
            int c = h * DK + wk * 16 + ni * 8 + 2 * tg;
            *(__half2*)&ctx[r0 * DD + c] =
                __floats2half2_rn(pacc[ni][0] * inv0, pacc[ni][1] * inv0);
            *(__half2*)&ctx[(r0 + 8) * DD + c] =
                __floats2half2_rn(pacc[ni][2] * inv1, pacc[ni][3] * inv1);
        }
    }
}

// ---------------------------------------------------------------------------
// LayerNorm(proj + residual) * g + b
// ---------------------------------------------------------------------------
__global__ __launch_bounds__(256) void ln_kernel(
    const float* __restrict__ proj, const float* __restrict__ resid,
    const float* __restrict__ gam, const float* __restrict__ bet,
    float* __restrict__ out)
{
    __shared__ float red[8];
    const int row = blockIdx.x;
    const int tid = threadIdx.x;
    const int c0 = tid * 4;
    const int lane = tid & 31, wid = tid >> 5;

    float4 pv = *(const float4*)(proj + (size_t)row * DD + c0);
    float4 rv = *(const float4*)(resid + (size_t)row * DD + c0);
    float x0 = pv.x + rv.x, x1 = pv.y + rv.y, x2 = pv.z + rv.z, x3 = pv.w + rv.w;

    float s = x0 + x1 + x2 + x3;
#pragma unroll
    for (int o = 16; o; o >>= 1) s += __shfl_xor_sync(0xffffffffu, s, o);
    if (lane == 0) red[wid] = s;
    __syncthreads();
    float tot = (lane < 8) ? red[lane] : 0.f;
#pragma unroll
    for (int o = 4; o; o >>= 1) tot += __shfl_xor_sync(0xffffffffu, tot, o);
    tot = __shfl_sync(0xffffffffu, tot, 0);
    float mean = tot * (1.f / 1024.f);

    float d0 = x0 - mean, d1 = x1 - mean, d2 = x2 - mean, d3 = x3 - mean;
    float sq = d0 * d0 + d1 * d1 + d2 * d2 + d3 * d3;
#pragma unroll
    for (int o = 16; o; o >>= 1) sq += __shfl_xor_sync(0xffffffffu, sq, o);
    __syncthreads();
    if (lane == 0) red[wid] = sq;
    __syncthreads();
    float tot2 = (lane < 8) ? red[lane] : 0.f;
#pragma unroll
    for (int o = 4; o; o >>= 1) tot2 += __shfl_xor_sync(0xffffffffu, tot2, o);
    tot2 = __shfl_sync(0xffffffffu, tot2, 0);
    float k = rsqrtf(tot2 * (1.f / 1024.f) + 1e-5f);

    float4 gv = *(const float4*)(gam + c0);
    float4 bv = *(const float4*)(bet + c0);
    float4 ov;
    ov.x = d0 * k * gv.x + bv.x;
    ov.y = d1 * k * gv.y + bv.y;
    ov.z = d2 * k * gv.z + bv.z;
    ov.w = d3 * k * gv.w + bv.w;
    *(float4*)&out[(size_t)row * DD + c0] = ov;
}

// ---------------------------------------------------------------------------
extern "C" void kernel_launch(void* const* d_in, const int* in_sizes, int n_in,
                              void* d_out, int out_size)
{
    const float* q    = (const float*)d_in[0];
    const float* k    = (const float*)d_in[1];
    const float* v    = (const float*)d_in[2];
    const int*   mask = (const int*)  d_in[3];
    const float* npm  = (const float*)d_in[4];
    const float* Wq   = (const float*)d_in[5];
    const float* bq   = (const float*)d_in[6];
    const float* Wk   = (const float*)d_in[7];
    const float* bk   = (const float*)d_in[8];
    const float* Wv   = (const float*)d_in[9];
    const float* bv   = (const float*)d_in[10];
    const float* Wf   = (const float*)d_in[11];
    const float* bf   = (const float*)d_in[12];
    const float* ln_g = (const float*)d_in[13];
    const float* ln_b = (const float*)d_in[14];

    float* out  = (float*)d_out;
    float* attn = out + (size_t)BB * LL * DD;

    __half *qh, *kh, *vhT, *ctx, *as, *ws;
    float *proj;
    uint8_t* mb;
    cudaGetSymbolAddress((void**)&qh,  g_qh);
    cudaGetSymbolAddress((void**)&kh,  g_kh);
    cudaGetSymbolAddress((void**)&vhT, g_vhT);
    cudaGetSymbolAddress((void**)&ctx, g_ctx);
    cudaGetSymbolAddress((void**)&proj, g_proj);
    cudaGetSymbolAddress((void**)&as,  g_as);
    cudaGetSymbolAddress((void**)&ws,  g_ws);
    cudaGetSymbolAddress((void**)&mb,  g_mb);

    cudaFuncSetAttribute(gemm_f16_1t, cudaFuncAttributeMaxDynamicSharedMemorySize, GEMM1_SMEM);
    cudaFuncSetAttribute(attn_kernel, cudaFuncAttributeMaxDynamicSharedMemorySize, ATT_SMEM);

    const int nA4 = ROWS_TOT * DD / 4;
    const int nW4 = DD * DD / 4;
    const int nM4 = BB * LL * LL / 4;
    dim3 gG(DD / 128, ROWS_TOT / 128);   // (8, 64)

    // mask -> byte (overlaps with projection pipeline)
    mask_byte<<<(nM4 + 255) / 256, 256>>>(mask, mb, nM4);

    // Q projection (scale 1/8 folded) -> fp16
    conv_f16<<<(nA4 + 255) / 256, 256>>>(q, as, nA4);
    conv_f16<<<(nW4 + 255) / 256, 256>>>(Wq, ws, nW4);
    gemm_f16_1t<<<gG, 512, GEMM1_SMEM>>>(as, ws, bq, npm, 0.125f, nullptr, qh, nullptr);
    // K projection -> fp16
    conv_f16<<<(nA4 + 255) / 256, 256>>>(k, as, nA4);
    conv_f16<<<(nW4 + 255) / 256, 256>>>(Wk, ws, nW4);
    gemm_f16_1t<<<gG, 512, GEMM1_SMEM>>>(as, ws, bk, npm, 1.0f, nullptr, kh, nullptr);
    // V projection -> transposed fp16 vhT
    conv_f16<<<(nA4 + 255) / 256, 256>>>(v, as, nA4);
    conv_f16<<<(nW4 + 255) / 256, 256>>>(Wv, ws, nW4);
    gemm_f16_1t<<<gG, 512, GEMM1_SMEM>>>(as, ws, bv, npm, 1.0f, nullptr, nullptr, vhT);

    // Fused attention, 64-row q-tiles (ctx out as fp16)
    attn_kernel<<<dim3(BB * HH, LL / 64), 512, ATT_SMEM>>>(
        qh, kh, vhT, mb, attn, ctx);

    // Output projection (ctx fp16 direct) -> fp32, then LN
    conv_f16<<<(nW4 + 255) / 256, 256>>>(Wf, ws, nW4);
    gemm_f16_1t<<<gG, 512, GEMM1_SMEM>>>(ctx, ws, bf, npm, 1.0f, proj, nullptr, nullptr);

    ln_kernel<<<ROWS_TOT, 256>>>(proj, q, ln_g, ln_b, out);
}